// round 13
// baseline (speedup 1.0000x reference)
#include <cuda_runtime.h>
#include <cuda_bf16.h>
#include <math.h>

#define NN 100000
#define NE 1600000
#define DD 128
#define CC 40
#define NL 3
#define NB_SCAN 98

__device__ float          g_h[(size_t)NN * DD];
__device__ __nv_bfloat16  g_c2b[(size_t)NN * DD];
__device__ __nv_bfloat16  g_aggb[(size_t)NN * DD];
__device__ __nv_bfloat16  g_wb[6 * DD * DD];
__device__ __nv_bfloat16  g_w0hi[DD * DD];
__device__ __nv_bfloat16  g_w0lo[DD * DD];
__device__ float g_dinv[NN];
__device__ int g_counts[NN], g_off[NN + 1], g_cur[NN], g_eidx[NE], g_part[128];

typedef unsigned long long u64;
typedef unsigned int u32;

__device__ __forceinline__ float siluf(float x) { return x / (1.0f + expf(-x)); }

__device__ __forceinline__ float warp_sum(float v) {
#pragma unroll
    for (int o = 16; o > 0; o >>= 1) v += __shfl_xor_sync(0xffffffffu, v, o);
    return v;
}
__device__ __forceinline__ float4 ldb4(const __nv_bfloat16* p) {
    uint2 u = *(const uint2*)p;
    __nv_bfloat162 a = *reinterpret_cast<const __nv_bfloat162*>(&u.x);
    __nv_bfloat162 b = *reinterpret_cast<const __nv_bfloat162*>(&u.y);
    float2 fa = __bfloat1622float2(a), fb = __bfloat1622float2(b);
    return make_float4(fa.x, fa.y, fb.x, fb.y);
}
__device__ __forceinline__ void stb4(__nv_bfloat16* p, float4 v) {
    __nv_bfloat162 a = __floats2bfloat162_rn(v.x, v.y), b = __floats2bfloat162_rn(v.z, v.w);
    uint2 u; u.x = *reinterpret_cast<u32*>(&a); u.y = *reinterpret_cast<u32*>(&b);
    *(uint2*)p = u;
}
__device__ __forceinline__ u32 pkbf2(float a, float b) {
    __nv_bfloat162 t = __floats2bfloat162_rn(a, b);
    return *reinterpret_cast<u32*>(&t);
}
__device__ __forceinline__ void ldsm4(u32* f, u32 addr) {
    asm volatile("ldmatrix.sync.aligned.m8n8.x4.shared.b16 {%0,%1,%2,%3}, [%4];"
                 : "=r"(f[0]), "=r"(f[1]), "=r"(f[2]), "=r"(f[3]) : "r"(addr));
}
__device__ __forceinline__ void ldsm2t(u32* f, u32 addr) {
    asm volatile("ldmatrix.sync.aligned.m8n8.x2.trans.shared.b16 {%0,%1}, [%2];"
                 : "=r"(f[0]), "=r"(f[1]) : "r"(addr));
}
__device__ __forceinline__ void mma16816(float* c, const u32* a, const u32* b) {
    asm volatile("mma.sync.aligned.m16n8k16.row.col.f32.bf16.bf16.f32 "
                 "{%0,%1,%2,%3}, {%4,%5,%6,%7}, {%8,%9}, {%0,%1,%2,%3};"
                 : "+f"(c[0]), "+f"(c[1]), "+f"(c[2]), "+f"(c[3])
                 : "r"(a[0]), "r"(a[1]), "r"(a[2]), "r"(a[3]), "r"(b[0]), "r"(b[1]));
}

// ---------------- weight conversion ----------------
__global__ void convert_w_kernel(const float* __restrict__ startW,
                                 const float* __restrict__ convW,
                                 const float* __restrict__ ffwW,
                                 __nv_bfloat16* __restrict__ w0hi,
                                 __nv_bfloat16* __restrict__ w0lo,
                                 __nv_bfloat16* __restrict__ wb) {
    const int i = blockIdx.x * blockDim.x + threadIdx.x;
    const int s = DD * DD, per = NL * DD * DD;
    if (i < s) {
        float v = startW[i];
        __nv_bfloat16 hi = __float2bfloat16(v);
        w0hi[i] = hi;
        w0lo[i] = __float2bfloat16(v - __bfloat162float(hi));
    } else if (i < s + per) {
        wb[i - s] = __float2bfloat16(convW[i - s]);
    } else if (i < s + 2 * per) {
        wb[i - s] = __float2bfloat16(ffwW[i - s - per]);
    }
}

// ---------------- CSR build ----------------
__global__ void zero_counts_kernel(int* c) { int i = blockIdx.x * blockDim.x + threadIdx.x; if (i < NN) c[i] = 0; }
__global__ void count_kernel(const int* __restrict__ col, int* __restrict__ c) {
    int e = blockIdx.x * blockDim.x + threadIdx.x; if (e < NE) atomicAdd(&c[col[e]], 1);
}
__global__ void __launch_bounds__(1024) scan_block_kernel(const int* __restrict__ counts,
                                                          int* __restrict__ off, int* __restrict__ part) {
    __shared__ int wsum[32];
    const int t = threadIdx.x, lane = t & 31, w = t >> 5;
    const int i = blockIdx.x * 1024 + t;
    const int v = (i < NN) ? counts[i] : 0;
    int x = v;
#pragma unroll
    for (int o = 1; o < 32; o <<= 1) { int y = __shfl_up_sync(0xffffffffu, x, o); if (lane >= o) x += y; }
    if (lane == 31) wsum[w] = x;
    __syncthreads();
    if (w == 0) {
        int y = wsum[lane];
#pragma unroll
        for (int o = 1; o < 32; o <<= 1) { int z = __shfl_up_sync(0xffffffffu, y, o); if (lane >= o) y += z; }
        wsum[lane] = y;
    }
    __syncthreads();
    const int incl = x + (w > 0 ? wsum[w - 1] : 0);
    if (i < NN) off[i + 1] = incl;
    if (t == 1023) part[blockIdx.x] = incl;
}
__global__ void scan_part_kernel(int* __restrict__ part, int* __restrict__ off) {
    const int lane = threadIdx.x;
    int carry = 0;
    for (int base = 0; base < 128; base += 32) {
        const int idx = base + lane;
        const int v = (idx < NB_SCAN) ? part[idx] : 0;
        int x = v;
#pragma unroll
        for (int o = 1; o < 32; o <<= 1) { int y = __shfl_up_sync(0xffffffffu, x, o); if (lane >= o) x += y; }
        if (idx < NB_SCAN) part[idx] = carry + x - v;
        carry += __shfl_sync(0xffffffffu, x, 31);
    }
    if (lane == 0) off[0] = 0;
}
// add_carry with dinv fused (dinv = rsqrt(counts+1))
__global__ void add_carry_kernel(const int* __restrict__ counts, int* __restrict__ off,
                                 const int* __restrict__ part, int* __restrict__ cur,
                                 float* __restrict__ dinv) {
    const int i = blockIdx.x * blockDim.x + threadIdx.x;
    if (i >= NN) return;
    const int c = counts[i];
    const int o = off[i + 1] + part[i >> 10];
    off[i + 1] = o; cur[i] = o - c;
    dinv[i] = rsqrtf((float)(c + 1));
}
__global__ void fill_kernel(const int* __restrict__ rowi, const int* __restrict__ coli,
                            int* __restrict__ cur, int* __restrict__ eidx) {
    int e = blockIdx.x * blockDim.x + threadIdx.x;
    if (e < NE) { int p = atomicAdd(&cur[coli[e]], 1); eidx[p] = rowi[e]; }
}

#define LDAB 136
#define LDC  132

// ---------------- conv GEMM: 128x128 block (measured 35.2us) ----------------
#define SM_G1 69632
__global__ void __launch_bounds__(256, 2) gemm1_kernel(
    const float* __restrict__ in, const __nv_bfloat16* __restrict__ Wb,
    const float* __restrict__ lng, const float* __restrict__ lnb,
    __nv_bfloat16* __restrict__ outb)
{
    extern __shared__ __align__(16) char smem[];
    __nv_bfloat16* Wsh = (__nv_bfloat16*)(smem);
    __nv_bfloat16* Ash = (__nv_bfloat16*)(smem + 34816);
    const int tid = threadIdx.x, wid = tid >> 5, lane = tid & 31;
    const int row0 = blockIdx.x * 128;

    {
        const int r = tid >> 1, half = tid & 1;
        const uint4* src = (const uint4*)(Wb + (size_t)r * DD + half * 64);
        uint4* dst = (uint4*)(Wsh + r * LDAB + half * 64);
#pragma unroll
        for (int j = 0; j < 8; j++) dst[j] = src[j];
    }
    {
        const float4 g4 = *(const float4*)(lng + lane * 4);
        const float4 b4 = *(const float4*)(lnb + lane * 4);
#pragma unroll
        for (int i = 0; i < 16; i++) {
            const int lr = wid * 16 + i;
            const int r = row0 + lr;
            float4 v = (r < NN) ? *(const float4*)(in + (size_t)r * DD + lane * 4)
                                : make_float4(0.f, 0.f, 0.f, 0.f);
            float s1 = warp_sum(v.x + v.y + v.z + v.w);
            float s2 = warp_sum(v.x * v.x + v.y * v.y + v.z * v.z + v.w * v.w);
            float mu  = s1 * (1.0f / 128.0f);
            float var = fmaxf(s2 * (1.0f / 128.0f) - mu * mu, 0.0f);
            float rs  = rsqrtf(var + 1e-5f);
            uint2 p;
            p.x = pkbf2((v.x - mu) * rs * g4.x + b4.x, (v.y - mu) * rs * g4.y + b4.y);
            p.y = pkbf2((v.z - mu) * rs * g4.z + b4.z, (v.w - mu) * rs * g4.w + b4.w);
            *(uint2*)(Ash + lr * LDAB + lane * 4) = p;
        }
    }
    __syncthreads();

    const int m0 = (wid >> 1) * 32, n0 = (wid & 1) * 64;
    const u32 a_base = (u32)__cvta_generic_to_shared(Ash);
    const u32 w_base = (u32)__cvta_generic_to_shared(Wsh);
    const int a_i = lane & 7, a_sel = lane >> 3;
    const int a_row = ((a_sel & 1) ? 8 : 0) + a_i;
    const int a_kof = (a_sel & 2) ? 8 : 0;
    const int b_row = lane & 15;

    float acc[2][8][4];
#pragma unroll
    for (int mt = 0; mt < 2; mt++)
#pragma unroll
        for (int nt = 0; nt < 8; nt++)
#pragma unroll
            for (int q = 0; q < 4; q++) acc[mt][nt][q] = 0.f;

#pragma unroll
    for (int k0 = 0; k0 < DD; k0 += 16) {
        u32 af[2][4], bf[8][2];
#pragma unroll
        for (int mt = 0; mt < 2; mt++)
            ldsm4(af[mt], a_base + (u32)((m0 + mt * 16 + a_row) * (LDAB * 2) + (k0 + a_kof) * 2));
#pragma unroll
        for (int nt = 0; nt < 8; nt++)
            ldsm2t(bf[nt], w_base + (u32)((k0 + b_row) * (LDAB * 2) + (n0 + nt * 8) * 2));
#pragma unroll
        for (int mt = 0; mt < 2; mt++)
#pragma unroll
            for (int nt = 0; nt < 8; nt++)
                mma16816(acc[mt][nt], af[mt], bf[nt]);
    }

    const int g = lane >> 2, t = lane & 3;
#pragma unroll
    for (int mt = 0; mt < 2; mt++) {
        const int r0 = row0 + m0 + mt * 16 + g;
        const int r1 = r0 + 8;
#pragma unroll
        for (int nt = 0; nt < 8; nt++) {
            const int col = n0 + nt * 8 + 2 * t;
            if (r0 < NN) *(u32*)(outb + (size_t)r0 * DD + col) = pkbf2(acc[mt][nt][0], acc[mt][nt][1]);
            if (r1 < NN) *(u32*)(outb + (size_t)r1 * DD + col) = pkbf2(acc[mt][nt][2], acc[mt][nt][3]);
        }
    }
}

// ---------------- unified HMMA GEMM (MODE 0 start / MODE 2 ffn) — R8-proven 64-row ----------------
#define SM_M0 104448
#define SM_M2 86016

template <int MODE>
__global__ void __launch_bounds__(256, 2) gemm_bf16_kernel(
    const float* __restrict__ in,
    const __nv_bfloat16* __restrict__ Whi,
    const __nv_bfloat16* __restrict__ Wlo,
    const float* __restrict__ bias,
    const float* __restrict__ lng,
    const float* __restrict__ lnb,
    const __nv_bfloat16* __restrict__ aggb,
    const float* __restrict__ convB,
    const float* __restrict__ alpha_g,
    const float* __restrict__ alpha_f,
    float* __restrict__ outf)
{
    extern __shared__ __align__(16) char smem[];
    __nv_bfloat16* Wsh  = (__nv_bfloat16*)(smem);
    __nv_bfloat16* Wlos = (__nv_bfloat16*)(smem + 34816);
    __nv_bfloat16* Ash  = (__nv_bfloat16*)(smem + (MODE == 0 ? 69632 : 34816));
    __nv_bfloat16* Alos = (__nv_bfloat16*)(smem + 87040);
    float*         H1sh = (float*)(smem + 52224);
    float*         Csh  = (float*)(smem);

    const int tid = threadIdx.x, wid = tid >> 5, lane = tid & 31;
    const int row0 = blockIdx.x * 64;
    float ag = 0.f;
    if (MODE == 2) ag = __ldg(alpha_g);

    {
        const int r = tid >> 1, half = tid & 1;
        const uint4* src = (const uint4*)(Whi + (size_t)r * DD + half * 64);
        uint4* dst = (uint4*)(Wsh + r * LDAB + half * 64);
#pragma unroll
        for (int j = 0; j < 8; j++) dst[j] = src[j];
        if (MODE == 0) {
            const uint4* s2 = (const uint4*)(Wlo + (size_t)r * DD + half * 64);
            uint4* d2 = (uint4*)(Wlos + r * LDAB + half * 64);
#pragma unroll
            for (int j = 0; j < 8; j++) d2[j] = s2[j];
        }
    }
    {
        float4 g4 = make_float4(0.f, 0.f, 0.f, 0.f);
        float4 b4 = make_float4(0.f, 0.f, 0.f, 0.f);
        float4 cb4 = make_float4(0.f, 0.f, 0.f, 0.f);
        if (MODE == 2) {
            g4 = *(const float4*)(lng + lane * 4);
            b4 = *(const float4*)(lnb + lane * 4);
            cb4 = *(const float4*)(convB + lane * 4);
        }
#pragma unroll
        for (int i = 0; i < 8; i++) {
            const int lr = wid * 8 + i;
            const int r = row0 + lr;
            float4 v = make_float4(0.f, 0.f, 0.f, 0.f);
            if (r < NN) v = *(const float4*)(in + (size_t)r * DD + lane * 4);
            if (MODE == 0) {
                __nv_bfloat16 hx = __float2bfloat16(v.x), hy = __float2bfloat16(v.y);
                __nv_bfloat16 hz = __float2bfloat16(v.z), hw = __float2bfloat16(v.w);
                uint2 phi;
                phi.x = pkbf2(__bfloat162float(hx), __bfloat162float(hy));
                phi.y = pkbf2(__bfloat162float(hz), __bfloat162float(hw));
                *(uint2*)(Ash + lr * LDAB + lane * 4) = phi;
                uint2 plo;
                plo.x = pkbf2(v.x - __bfloat162float(hx), v.y - __bfloat162float(hy));
                plo.y = pkbf2(v.z - __bfloat162float(hz), v.w - __bfloat162float(hw));
                *(uint2*)(Alos + lr * LDAB + lane * 4) = plo;
                continue;
            }
            float4 av = make_float4(0.f, 0.f, 0.f, 0.f);
            if (r < NN) av = ldb4(aggb + (size_t)r * DD + lane * 4);
            v.x = fmaf(ag, siluf(av.x + cb4.x), v.x);
            v.y = fmaf(ag, siluf(av.y + cb4.y), v.y);
            v.z = fmaf(ag, siluf(av.z + cb4.z), v.z);
            v.w = fmaf(ag, siluf(av.w + cb4.w), v.w);
            *(float4*)(H1sh + lr * LDC + lane * 4) = v;
            float s1 = warp_sum(v.x + v.y + v.z + v.w);
            float s2 = warp_sum(v.x * v.x + v.y * v.y + v.z * v.z + v.w * v.w);
            float mu  = s1 * (1.0f / 128.0f);
            float var = fmaxf(s2 * (1.0f / 128.0f) - mu * mu, 0.0f);
            float rs  = rsqrtf(var + 1e-5f);
            uint2 p;
            p.x = pkbf2((v.x - mu) * rs * g4.x + b4.x, (v.y - mu) * rs * g4.y + b4.y);
            p.y = pkbf2((v.z - mu) * rs * g4.z + b4.z, (v.w - mu) * rs * g4.w + b4.w);
            *(uint2*)(Ash + lr * LDAB + lane * 4) = p;
        }
    }
    __syncthreads();

    const int m0 = (wid >> 2) * 32, n0 = (wid & 3) * 32;
    const u32 a_base  = (u32)__cvta_generic_to_shared(Ash);
    const u32 al_base = (u32)__cvta_generic_to_shared(Alos);
    const u32 w_base  = (u32)__cvta_generic_to_shared(Wsh);
    const u32 wl_base = (u32)__cvta_generic_to_shared(Wlos);
    const int a_i = lane & 7, a_sel = lane >> 3;
    const int a_row = ((a_sel & 1) ? 8 : 0) + a_i;
    const int a_kof = (a_sel & 2) ? 8 : 0;
    const int b_row = lane & 15;

    float acc[2][4][4];
#pragma unroll
    for (int mt = 0; mt < 2; mt++)
#pragma unroll
        for (int nt = 0; nt < 4; nt++)
#pragma unroll
            for (int q = 0; q < 4; q++) acc[mt][nt][q] = 0.f;

    if (MODE == 0) {
#pragma unroll
        for (int k0 = 0; k0 < DD; k0 += 16) {
            u32 ah[2][4], al[2][4], bh[4][2], bl[4][2];
#pragma unroll
            for (int mt = 0; mt < 2; mt++) {
                const u32 off = (u32)((m0 + mt * 16 + a_row) * (LDAB * 2) + (k0 + a_kof) * 2);
                ldsm4(ah[mt], a_base + off);
                ldsm4(al[mt], al_base + off);
            }
#pragma unroll
            for (int nt = 0; nt < 4; nt++) {
                const u32 off = (u32)((k0 + b_row) * (LDAB * 2) + (n0 + nt * 8) * 2);
                ldsm2t(bh[nt], w_base + off);
                ldsm2t(bl[nt], wl_base + off);
            }
#pragma unroll
            for (int mt = 0; mt < 2; mt++)
#pragma unroll
                for (int nt = 0; nt < 4; nt++) {
                    mma16816(acc[mt][nt], ah[mt], bh[nt]);
                    mma16816(acc[mt][nt], ah[mt], bl[nt]);
                    mma16816(acc[mt][nt], al[mt], bh[nt]);
                }
        }
    } else {
        u32 af[2][2][4], bf[2][4][2];
#pragma unroll
        for (int mt = 0; mt < 2; mt++)
            ldsm4(af[0][mt], a_base + (u32)((m0 + mt * 16 + a_row) * (LDAB * 2) + a_kof * 2));
#pragma unroll
        for (int nt = 0; nt < 4; nt++)
            ldsm2t(bf[0][nt], w_base + (u32)(b_row * (LDAB * 2) + (n0 + nt * 8) * 2));
#pragma unroll
        for (int ks = 0; ks < 8; ks++) {
            const int cur = ks & 1;
            if (ks < 7) {
                const int k1 = (ks + 1) * 16;
#pragma unroll
                for (int mt = 0; mt < 2; mt++)
                    ldsm4(af[cur ^ 1][mt], a_base + (u32)((m0 + mt * 16 + a_row) * (LDAB * 2) + (k1 + a_kof) * 2));
#pragma unroll
                for (int nt = 0; nt < 4; nt++)
                    ldsm2t(bf[cur ^ 1][nt], w_base + (u32)((k1 + b_row) * (LDAB * 2) + (n0 + nt * 8) * 2));
            }
#pragma unroll
            for (int mt = 0; mt < 2; mt++)
#pragma unroll
                for (int nt = 0; nt < 4; nt++)
                    mma16816(acc[mt][nt], af[cur][mt], bf[cur][nt]);
        }
    }

    __syncthreads();
    {
        const int g = lane >> 2, t = lane & 3;
#pragma unroll
        for (int mt = 0; mt < 2; mt++)
#pragma unroll
            for (int nt = 0; nt < 4; nt++) {
                const int row = m0 + mt * 16 + g;
                const int col = n0 + nt * 8 + 2 * t;
                *(float2*)(Csh + row * LDC + col)       = make_float2(acc[mt][nt][0], acc[mt][nt][1]);
                *(float2*)(Csh + (row + 8) * LDC + col) = make_float2(acc[mt][nt][2], acc[mt][nt][3]);
            }
    }
    __syncthreads();

    const float4 bias4 = *(const float4*)(bias + lane * 4);
    float af2 = 0.f;
    if (MODE == 2) af2 = __ldg(alpha_f);

#pragma unroll
    for (int i = 0; i < 8; i++) {
        const int lr = wid * 8 + i;
        const int r = row0 + lr;
        if (r >= NN) continue;
        float4 o = *(const float4*)(Csh + lr * LDC + lane * 4);
        if (MODE == 0) {
            o.x = siluf(o.x + bias4.x);
            o.y = siluf(o.y + bias4.y);
            o.z = siluf(o.z + bias4.z);
            o.w = siluf(o.w + bias4.w);
        } else {
            const float4 h1 = *(const float4*)(H1sh + lr * LDC + lane * 4);
            o.x = fmaf(af2, siluf(o.x + bias4.x), h1.x);
            o.y = fmaf(af2, siluf(o.y + bias4.y), h1.y);
            o.z = fmaf(af2, siluf(o.z + bias4.z), h1.z);
            o.w = fmaf(af2, siluf(o.w + bias4.w), h1.w);
        }
        *(float4*)(outf + (size_t)r * DD + lane * 4) = o;
    }
}

// ---------------- CSR gather: warp per node, 4-way (R8-proven) ----------------
__global__ void __launch_bounds__(256) gather_kernel(
    const int* __restrict__ off, const int* __restrict__ eidx,
    const float* __restrict__ dinv, const __nv_bfloat16* __restrict__ c2b,
    __nv_bfloat16* __restrict__ aggb)
{
    const int n = blockIdx.x * 8 + (threadIdx.x >> 5);
    if (n >= NN) return;
    const int lane = threadIdx.x & 31;
    const int s = __ldg(off + n), e = __ldg(off + n + 1);
    const float dn = __ldg(dinv + n);

    float4 acc = ldb4(c2b + (size_t)n * DD + lane * 4);
    acc.x *= dn; acc.y *= dn; acc.z *= dn; acc.w *= dn;
    for (int j0 = s; j0 < e; j0 += 32) {
        const int jn = min(32, e - j0);
        int eid = 0; float wv = 0.f;
        if (lane < jn) { eid = __ldg(eidx + j0 + lane); wv = __ldg(dinv + eid); }
        int t = 0;
        for (; t + 4 <= jn; t += 4) {
            const int r0 = __shfl_sync(0xffffffffu, eid, t);
            const int r1 = __shfl_sync(0xffffffffu, eid, t + 1);
            const int r2 = __shfl_sync(0xffffffffu, eid, t + 2);
            const int r3 = __shfl_sync(0xffffffffu, eid, t + 3);
            const float w0 = __shfl_sync(0xffffffffu, wv, t);
            const float w1 = __shfl_sync(0xffffffffu, wv, t + 1);
            const float w2 = __shfl_sync(0xffffffffu, wv, t + 2);
            const float w3 = __shfl_sync(0xffffffffu, wv, t + 3);
            const float4 v0 = ldb4(c2b + (size_t)r0 * DD + lane * 4);
            const float4 v1 = ldb4(c2b + (size_t)r1 * DD + lane * 4);
            const float4 v2 = ldb4(c2b + (size_t)r2 * DD + lane * 4);
            const float4 v3 = ldb4(c2b + (size_t)r3 * DD + lane * 4);
            acc.x += w0 * v0.x + w1 * v1.x + w2 * v2.x + w3 * v3.x;
            acc.y += w0 * v0.y + w1 * v1.y + w2 * v2.y + w3 * v3.y;
            acc.z += w0 * v0.z + w1 * v1.z + w2 * v2.z + w3 * v3.z;
            acc.w += w0 * v0.w + w1 * v1.w + w2 * v2.w + w3 * v3.w;
        }
        for (; t < jn; t++) {
            const int rr = __shfl_sync(0xffffffffu, eid, t);
            const float w = __shfl_sync(0xffffffffu, wv, t);
            const float4 v = ldb4(c2b + (size_t)rr * DD + lane * 4);
            acc.x = fmaf(w, v.x, acc.x); acc.y = fmaf(w, v.y, acc.y);
            acc.z = fmaf(w, v.z, acc.z); acc.w = fmaf(w, v.w, acc.w);
        }
    }
    acc.x *= dn; acc.y *= dn; acc.z *= dn; acc.w *= dn;
    stb4(aggb + (size_t)n * DD + lane * 4, acc);
}

// ---------------- final: logits + log_softmax ----------------
__global__ void __launch_bounds__(128) final_kernel(
    const float* __restrict__ h, const float* __restrict__ Wf,
    const float* __restrict__ fb, float* __restrict__ out)
{
    __shared__ float Wsh[DD * CC];
    __shared__ float bsh[CC];
    __shared__ float rowbuf[4][DD];
    const int tid = threadIdx.x;
    for (int i = tid; i < DD * CC; i += 128) Wsh[i] = Wf[i];
    if (tid < CC) bsh[tid] = fb[tid];
    __syncthreads();

    const int wid = tid >> 5, lane = tid & 31;
    const int rbase = blockIdx.x * 32 + wid * 8;
    const bool has1 = (lane < CC - 32);

    for (int ri = 0; ri < 8; ri++) {
        const int r = rbase + ri;
        if (r >= NN) return;
        float4 v = *(const float4*)(h + (size_t)r * DD + lane * 4);
        *(float4*)(&rowbuf[wid][lane * 4]) = v;
        __syncwarp();
        float acc0 = bsh[lane];
        float acc1 = has1 ? bsh[32 + lane] : 0.f;
#pragma unroll 4
        for (int k = 0; k < DD; k++) {
            float hv = rowbuf[wid][k];
            acc0 = fmaf(hv, Wsh[k * CC + lane], acc0);
            if (has1) acc1 = fmaf(hv, Wsh[k * CC + 32 + lane], acc1);
        }
        float m = has1 ? fmaxf(acc0, acc1) : acc0;
#pragma unroll
        for (int o = 16; o > 0; o >>= 1) m = fmaxf(m, __shfl_xor_sync(0xffffffffu, m, o));
        float s = expf(acc0 - m) + (has1 ? expf(acc1 - m) : 0.f);
#pragma unroll
        for (int o = 16; o > 0; o >>= 1) s += __shfl_xor_sync(0xffffffffu, s, o);
        const float ls = logf(s);
        out[(size_t)r * CC + lane] = acc0 - m - ls;
        if (has1) out[(size_t)r * CC + 32 + lane] = acc1 - m - ls;
        __syncwarp();
    }
}

// ---------------- launch ----------------
extern "C" void kernel_launch(void* const* d_in, const int* in_sizes, int n_in,
                              void* d_out, int out_size)
{
    const float* x       = (const float*)d_in[0];
    const int*   ei      = (const int*)  d_in[1];
    const float* start_W = (const float*)d_in[2];
    const float* start_b = (const float*)d_in[3];
    const float* ln1_g   = (const float*)d_in[4];
    const float* ln1_b   = (const float*)d_in[5];
    const float* convW   = (const float*)d_in[6];
    const float* convB   = (const float*)d_in[7];
    const float* alpha_g = (const float*)d_in[8];
    const float* ln2_g   = (const float*)d_in[9];
    const float* ln2_b   = (const float*)d_in[10];
    const float* ffwW    = (const float*)d_in[11];
    const float* ffwB    = (const float*)d_in[12];
    const float* alpha_f = (const float*)d_in[13];
    const float* final_W = (const float*)d_in[14];
    const float* final_b = (const float*)d_in[15];
    float* out = (float*)d_out;

    float *h, *dinv;
    __nv_bfloat16 *c2b, *aggb, *wb, *w0hi, *w0lo;
    int *counts, *off, *cur, *eidx, *part;
    cudaGetSymbolAddress((void**)&h, g_h);
    cudaGetSymbolAddress((void**)&c2b, g_c2b);
    cudaGetSymbolAddress((void**)&aggb, g_aggb);
    cudaGetSymbolAddress((void**)&wb, g_wb);
    cudaGetSymbolAddress((void**)&w0hi, g_w0hi);
    cudaGetSymbolAddress((void**)&w0lo, g_w0lo);
    cudaGetSymbolAddress((void**)&dinv, g_dinv);
    cudaGetSymbolAddress((void**)&counts, g_counts);
    cudaGetSymbolAddress((void**)&off, g_off);
    cudaGetSymbolAddress((void**)&cur, g_cur);
    cudaGetSymbolAddress((void**)&eidx, g_eidx);
    cudaGetSymbolAddress((void**)&part, g_part);

    const int* rowi = ei;
    const int* coli = ei + NE;

    cudaFuncSetAttribute(gemm_bf16_kernel<0>, cudaFuncAttributeMaxDynamicSharedMemorySize, SM_M0);
    cudaFuncSetAttribute(gemm_bf16_kernel<2>, cudaFuncAttributeMaxDynamicSharedMemorySize, SM_M2);
    cudaFuncSetAttribute(gemm1_kernel, cudaFuncAttributeMaxDynamicSharedMemorySize, SM_G1);

    const int GB = (NN + 63) / 64;
    const int G1 = (NN + 127) / 128;
    const int NW = DD * DD + 2 * NL * DD * DD;

    // Reordered so capture slot #4 = gemm_bf16<0> (start GEMM; never measured).
    convert_w_kernel<<<(NW + 255) / 256, 256>>>(start_W, convW, ffwW, w0hi, w0lo, wb);   // 1
    zero_counts_kernel<<<(NN + 255) / 256, 256>>>(counts);                                // 2
    count_kernel<<<(NE + 255) / 256, 256>>>(coli, counts);                                // 3
    gemm_bf16_kernel<0><<<GB, 256, SM_M0>>>(x, w0hi, w0lo, start_b,                       // 4 (capture)
                                            nullptr, nullptr, nullptr, nullptr,
                                            nullptr, nullptr, h);
    scan_block_kernel<<<NB_SCAN, 1024>>>(counts, off, part);                              // 5
    scan_part_kernel<<<1, 32>>>(part, off);                                               // 6
    add_carry_kernel<<<(NN + 255) / 256, 256>>>(counts, off, part, cur, dinv);            // 7 (dinv fused)
    fill_kernel<<<(NE + 255) / 256, 256>>>(rowi, coli, cur, eidx);                        // 8

    for (int i = 0; i < NL; i++) {
        gemm1_kernel<<<G1, 256, SM_G1>>>(h, wb + (size_t)i * DD * DD,
                                         ln1_g + i * DD, ln1_b + i * DD, c2b);
        gather_kernel<<<(NN + 7) / 8, 256>>>(off, eidx, dinv, c2b, aggb);
        gemm_bf16_kernel<2><<<GB, 256, SM_M2>>>(h, wb + (size_t)(NL + i) * DD * DD, nullptr,
                                                ffwB + i * DD,
                                                ln2_g + i * DD, ln2_b + i * DD,
                                                aggb, convB + i * DD,
                                                alpha_g + i, alpha_f + i, h);
    }

    final_kernel<<<(NN + 31) / 32, 128>>>(h, final_W, final_b, out);
}

// round 14
// speedup vs baseline: 1.0218x; 1.0218x over previous
#include <cuda_runtime.h>
#include <cuda_bf16.h>
#include <math.h>

#define NN 100000
#define NE 1600000
#define DD 128
#define CC 40
#define NL 3
#define NB_SCAN 98

__device__ float          g_h[(size_t)NN * DD];
__device__ __nv_bfloat16  g_c2b[(size_t)NN * DD];
__device__ __nv_bfloat16  g_aggb[(size_t)NN * DD];
__device__ __nv_bfloat16  g_wb[6 * DD * DD];
__device__ __nv_bfloat16  g_w0hi[DD * DD];
__device__ __nv_bfloat16  g_w0lo[DD * DD];
__device__ float g_dinv[NN];
__device__ int g_counts[NN], g_off[NN + 1], g_cur[NN], g_eidx[NE], g_part[128];

typedef unsigned long long u64;
typedef unsigned int u32;

__device__ __forceinline__ float siluf(float x) { return x / (1.0f + expf(-x)); }

__device__ __forceinline__ float warp_sum(float v) {
#pragma unroll
    for (int o = 16; o > 0; o >>= 1) v += __shfl_xor_sync(0xffffffffu, v, o);
    return v;
}
__device__ __forceinline__ float4 ldb4(const __nv_bfloat16* p) {
    uint2 u = *(const uint2*)p;
    __nv_bfloat162 a = *reinterpret_cast<const __nv_bfloat162*>(&u.x);
    __nv_bfloat162 b = *reinterpret_cast<const __nv_bfloat162*>(&u.y);
    float2 fa = __bfloat1622float2(a), fb = __bfloat1622float2(b);
    return make_float4(fa.x, fa.y, fb.x, fb.y);
}
__device__ __forceinline__ u32 pkbf2(float a, float b) {
    __nv_bfloat162 t = __floats2bfloat162_rn(a, b);
    return *reinterpret_cast<u32*>(&t);
}
// unpack 8 bf16 (uint4) -> 8 fp32
__device__ __forceinline__ void unp8(uint4 u, float* o) {
    __nv_bfloat162 p0 = *reinterpret_cast<__nv_bfloat162*>(&u.x);
    __nv_bfloat162 p1 = *reinterpret_cast<__nv_bfloat162*>(&u.y);
    __nv_bfloat162 p2 = *reinterpret_cast<__nv_bfloat162*>(&u.z);
    __nv_bfloat162 p3 = *reinterpret_cast<__nv_bfloat162*>(&u.w);
    float2 f0 = __bfloat1622float2(p0), f1 = __bfloat1622float2(p1);
    float2 f2 = __bfloat1622float2(p2), f3 = __bfloat1622float2(p3);
    o[0] = f0.x; o[1] = f0.y; o[2] = f1.x; o[3] = f1.y;
    o[4] = f2.x; o[5] = f2.y; o[6] = f3.x; o[7] = f3.y;
}
__device__ __forceinline__ void ldsm4(u32* f, u32 addr) {
    asm volatile("ldmatrix.sync.aligned.m8n8.x4.shared.b16 {%0,%1,%2,%3}, [%4];"
                 : "=r"(f[0]), "=r"(f[1]), "=r"(f[2]), "=r"(f[3]) : "r"(addr));
}
__device__ __forceinline__ void ldsm2t(u32* f, u32 addr) {
    asm volatile("ldmatrix.sync.aligned.m8n8.x2.trans.shared.b16 {%0,%1}, [%2];"
                 : "=r"(f[0]), "=r"(f[1]) : "r"(addr));
}
__device__ __forceinline__ void mma16816(float* c, const u32* a, const u32* b) {
    asm volatile("mma.sync.aligned.m16n8k16.row.col.f32.bf16.bf16.f32 "
                 "{%0,%1,%2,%3}, {%4,%5,%6,%7}, {%8,%9}, {%0,%1,%2,%3};"
                 : "+f"(c[0]), "+f"(c[1]), "+f"(c[2]), "+f"(c[3])
                 : "r"(a[0]), "r"(a[1]), "r"(a[2]), "r"(a[3]), "r"(b[0]), "r"(b[1]));
}

// ---------------- weight conversion ----------------
__global__ void convert_w_kernel(const float* __restrict__ startW,
                                 const float* __restrict__ convW,
                                 const float* __restrict__ ffwW,
                                 __nv_bfloat16* __restrict__ w0hi,
                                 __nv_bfloat16* __restrict__ w0lo,
                                 __nv_bfloat16* __restrict__ wb) {
    const int i = blockIdx.x * blockDim.x + threadIdx.x;
    const int s = DD * DD, per = NL * DD * DD;
    if (i < s) {
        float v = startW[i];
        __nv_bfloat16 hi = __float2bfloat16(v);
        w0hi[i] = hi;
        w0lo[i] = __float2bfloat16(v - __bfloat162float(hi));
    } else if (i < s + per) {
        wb[i - s] = __float2bfloat16(convW[i - s]);
    } else if (i < s + 2 * per) {
        wb[i - s] = __float2bfloat16(ffwW[i - s - per]);
    }
}

// ---------------- CSR build ----------------
__global__ void zero_counts_kernel(int* c) { int i = blockIdx.x * blockDim.x + threadIdx.x; if (i < NN) c[i] = 0; }
__global__ void count_kernel(const int* __restrict__ col, int* __restrict__ c) {
    int e = blockIdx.x * blockDim.x + threadIdx.x; if (e < NE) atomicAdd(&c[col[e]], 1);
}
__global__ void __launch_bounds__(1024) scan_block_kernel(const int* __restrict__ counts,
                                                          int* __restrict__ off, int* __restrict__ part) {
    __shared__ int wsum[32];
    const int t = threadIdx.x, lane = t & 31, w = t >> 5;
    const int i = blockIdx.x * 1024 + t;
    const int v = (i < NN) ? counts[i] : 0;
    int x = v;
#pragma unroll
    for (int o = 1; o < 32; o <<= 1) { int y = __shfl_up_sync(0xffffffffu, x, o); if (lane >= o) x += y; }
    if (lane == 31) wsum[w] = x;
    __syncthreads();
    if (w == 0) {
        int y = wsum[lane];
#pragma unroll
        for (int o = 1; o < 32; o <<= 1) { int z = __shfl_up_sync(0xffffffffu, y, o); if (lane >= o) y += z; }
        wsum[lane] = y;
    }
    __syncthreads();
    const int incl = x + (w > 0 ? wsum[w - 1] : 0);
    if (i < NN) off[i + 1] = incl;
    if (t == 1023) part[blockIdx.x] = incl;
}
__global__ void scan_part_kernel(int* __restrict__ part, int* __restrict__ off) {
    const int lane = threadIdx.x;
    int carry = 0;
    for (int base = 0; base < 128; base += 32) {
        const int idx = base + lane;
        const int v = (idx < NB_SCAN) ? part[idx] : 0;
        int x = v;
#pragma unroll
        for (int o = 1; o < 32; o <<= 1) { int y = __shfl_up_sync(0xffffffffu, x, o); if (lane >= o) x += y; }
        if (idx < NB_SCAN) part[idx] = carry + x - v;
        carry += __shfl_sync(0xffffffffu, x, 31);
    }
    if (lane == 0) off[0] = 0;
}
__global__ void add_carry_kernel(const int* __restrict__ counts, int* __restrict__ off,
                                 const int* __restrict__ part, int* __restrict__ cur,
                                 float* __restrict__ dinv) {
    const int i = blockIdx.x * blockDim.x + threadIdx.x;
    if (i >= NN) return;
    const int c = counts[i];
    const int o = off[i + 1] + part[i >> 10];
    off[i + 1] = o; cur[i] = o - c;
    dinv[i] = rsqrtf((float)(c + 1));
}
__global__ void fill_kernel(const int* __restrict__ rowi, const int* __restrict__ coli,
                            int* __restrict__ cur, int* __restrict__ eidx) {
    int e = blockIdx.x * blockDim.x + threadIdx.x;
    if (e < NE) { int p = atomicAdd(&cur[coli[e]], 1); eidx[p] = rowi[e]; }
}

#define LDAB 136
#define LDC  132

// ---------------- conv GEMM: 128x128 block (measured 35.2us) ----------------
#define SM_G1 69632
__global__ void __launch_bounds__(256, 2) gemm1_kernel(
    const float* __restrict__ in, const __nv_bfloat16* __restrict__ Wb,
    const float* __restrict__ lng, const float* __restrict__ lnb,
    __nv_bfloat16* __restrict__ outb)
{
    extern __shared__ __align__(16) char smem[];
    __nv_bfloat16* Wsh = (__nv_bfloat16*)(smem);
    __nv_bfloat16* Ash = (__nv_bfloat16*)(smem + 34816);
    const int tid = threadIdx.x, wid = tid >> 5, lane = tid & 31;
    const int row0 = blockIdx.x * 128;

    {
        const int r = tid >> 1, half = tid & 1;
        const uint4* src = (const uint4*)(Wb + (size_t)r * DD + half * 64);
        uint4* dst = (uint4*)(Wsh + r * LDAB + half * 64);
#pragma unroll
        for (int j = 0; j < 8; j++) dst[j] = src[j];
    }
    {
        const float4 g4 = *(const float4*)(lng + lane * 4);
        const float4 b4 = *(const float4*)(lnb + lane * 4);
#pragma unroll
        for (int i = 0; i < 16; i++) {
            const int lr = wid * 16 + i;
            const int r = row0 + lr;
            float4 v = (r < NN) ? *(const float4*)(in + (size_t)r * DD + lane * 4)
                                : make_float4(0.f, 0.f, 0.f, 0.f);
            float s1 = warp_sum(v.x + v.y + v.z + v.w);
            float s2 = warp_sum(v.x * v.x + v.y * v.y + v.z * v.z + v.w * v.w);
            float mu  = s1 * (1.0f / 128.0f);
            float var = fmaxf(s2 * (1.0f / 128.0f) - mu * mu, 0.0f);
            float rs  = rsqrtf(var + 1e-5f);
            uint2 p;
            p.x = pkbf2((v.x - mu) * rs * g4.x + b4.x, (v.y - mu) * rs * g4.y + b4.y);
            p.y = pkbf2((v.z - mu) * rs * g4.z + b4.z, (v.w - mu) * rs * g4.w + b4.w);
            *(uint2*)(Ash + lr * LDAB + lane * 4) = p;
        }
    }
    __syncthreads();

    const int m0 = (wid >> 1) * 32, n0 = (wid & 1) * 64;
    const u32 a_base = (u32)__cvta_generic_to_shared(Ash);
    const u32 w_base = (u32)__cvta_generic_to_shared(Wsh);
    const int a_i = lane & 7, a_sel = lane >> 3;
    const int a_row = ((a_sel & 1) ? 8 : 0) + a_i;
    const int a_kof = (a_sel & 2) ? 8 : 0;
    const int b_row = lane & 15;

    float acc[2][8][4];
#pragma unroll
    for (int mt = 0; mt < 2; mt++)
#pragma unroll
        for (int nt = 0; nt < 8; nt++)
#pragma unroll
            for (int q = 0; q < 4; q++) acc[mt][nt][q] = 0.f;

#pragma unroll
    for (int k0 = 0; k0 < DD; k0 += 16) {
        u32 af[2][4], bf[8][2];
#pragma unroll
        for (int mt = 0; mt < 2; mt++)
            ldsm4(af[mt], a_base + (u32)((m0 + mt * 16 + a_row) * (LDAB * 2) + (k0 + a_kof) * 2));
#pragma unroll
        for (int nt = 0; nt < 8; nt++)
            ldsm2t(bf[nt], w_base + (u32)((k0 + b_row) * (LDAB * 2) + (n0 + nt * 8) * 2));
#pragma unroll
        for (int mt = 0; mt < 2; mt++)
#pragma unroll
            for (int nt = 0; nt < 8; nt++)
                mma16816(acc[mt][nt], af[mt], bf[nt]);
    }

    const int g = lane >> 2, t = lane & 3;
#pragma unroll
    for (int mt = 0; mt < 2; mt++) {
        const int r0 = row0 + m0 + mt * 16 + g;
        const int r1 = r0 + 8;
#pragma unroll
        for (int nt = 0; nt < 8; nt++) {
            const int col = n0 + nt * 8 + 2 * t;
            if (r0 < NN) *(u32*)(outb + (size_t)r0 * DD + col) = pkbf2(acc[mt][nt][0], acc[mt][nt][1]);
            if (r1 < NN) *(u32*)(outb + (size_t)r1 * DD + col) = pkbf2(acc[mt][nt][2], acc[mt][nt][3]);
        }
    }
}

// ---------------- unified HMMA GEMM (MODE 0 start / MODE 2 ffn) — R8-proven 64-row ----------------
#define SM_M0 104448
#define SM_M2 86016

template <int MODE>
__global__ void __launch_bounds__(256, 2) gemm_bf16_kernel(
    const float* __restrict__ in,
    const __nv_bfloat16* __restrict__ Whi,
    const __nv_bfloat16* __restrict__ Wlo,
    const float* __restrict__ bias,
    const float* __restrict__ lng,
    const float* __restrict__ lnb,
    const __nv_bfloat16* __restrict__ aggb,
    const float* __restrict__ convB,
    const float* __restrict__ alpha_g,
    const float* __restrict__ alpha_f,
    float* __restrict__ outf)
{
    extern __shared__ __align__(16) char smem[];
    __nv_bfloat16* Wsh  = (__nv_bfloat16*)(smem);
    __nv_bfloat16* Wlos = (__nv_bfloat16*)(smem + 34816);
    __nv_bfloat16* Ash  = (__nv_bfloat16*)(smem + (MODE == 0 ? 69632 : 34816));
    __nv_bfloat16* Alos = (__nv_bfloat16*)(smem + 87040);
    float*         H1sh = (float*)(smem + 52224);
    float*         Csh  = (float*)(smem);

    const int tid = threadIdx.x, wid = tid >> 5, lane = tid & 31;
    const int row0 = blockIdx.x * 64;
    float ag = 0.f;
    if (MODE == 2) ag = __ldg(alpha_g);

    {
        const int r = tid >> 1, half = tid & 1;
        const uint4* src = (const uint4*)(Whi + (size_t)r * DD + half * 64);
        uint4* dst = (uint4*)(Wsh + r * LDAB + half * 64);
#pragma unroll
        for (int j = 0; j < 8; j++) dst[j] = src[j];
        if (MODE == 0) {
            const uint4* s2 = (const uint4*)(Wlo + (size_t)r * DD + half * 64);
            uint4* d2 = (uint4*)(Wlos + r * LDAB + half * 64);
#pragma unroll
            for (int j = 0; j < 8; j++) d2[j] = s2[j];
        }
    }
    {
        float4 g4 = make_float4(0.f, 0.f, 0.f, 0.f);
        float4 b4 = make_float4(0.f, 0.f, 0.f, 0.f);
        float4 cb4 = make_float4(0.f, 0.f, 0.f, 0.f);
        if (MODE == 2) {
            g4 = *(const float4*)(lng + lane * 4);
            b4 = *(const float4*)(lnb + lane * 4);
            cb4 = *(const float4*)(convB + lane * 4);
        }
#pragma unroll
        for (int i = 0; i < 8; i++) {
            const int lr = wid * 8 + i;
            const int r = row0 + lr;
            float4 v = make_float4(0.f, 0.f, 0.f, 0.f);
            if (r < NN) v = *(const float4*)(in + (size_t)r * DD + lane * 4);
            if (MODE == 0) {
                __nv_bfloat16 hx = __float2bfloat16(v.x), hy = __float2bfloat16(v.y);
                __nv_bfloat16 hz = __float2bfloat16(v.z), hw = __float2bfloat16(v.w);
                uint2 phi;
                phi.x = pkbf2(__bfloat162float(hx), __bfloat162float(hy));
                phi.y = pkbf2(__bfloat162float(hz), __bfloat162float(hw));
                *(uint2*)(Ash + lr * LDAB + lane * 4) = phi;
                uint2 plo;
                plo.x = pkbf2(v.x - __bfloat162float(hx), v.y - __bfloat162float(hy));
                plo.y = pkbf2(v.z - __bfloat162float(hz), v.w - __bfloat162float(hw));
                *(uint2*)(Alos + lr * LDAB + lane * 4) = plo;
                continue;
            }
            float4 av = make_float4(0.f, 0.f, 0.f, 0.f);
            if (r < NN) av = ldb4(aggb + (size_t)r * DD + lane * 4);
            v.x = fmaf(ag, siluf(av.x + cb4.x), v.x);
            v.y = fmaf(ag, siluf(av.y + cb4.y), v.y);
            v.z = fmaf(ag, siluf(av.z + cb4.z), v.z);
            v.w = fmaf(ag, siluf(av.w + cb4.w), v.w);
            *(float4*)(H1sh + lr * LDC + lane * 4) = v;
            float s1 = warp_sum(v.x + v.y + v.z + v.w);
            float s2 = warp_sum(v.x * v.x + v.y * v.y + v.z * v.z + v.w * v.w);
            float mu  = s1 * (1.0f / 128.0f);
            float var = fmaxf(s2 * (1.0f / 128.0f) - mu * mu, 0.0f);
            float rs  = rsqrtf(var + 1e-5f);
            uint2 p;
            p.x = pkbf2((v.x - mu) * rs * g4.x + b4.x, (v.y - mu) * rs * g4.y + b4.y);
            p.y = pkbf2((v.z - mu) * rs * g4.z + b4.z, (v.w - mu) * rs * g4.w + b4.w);
            *(uint2*)(Ash + lr * LDAB + lane * 4) = p;
        }
    }
    __syncthreads();

    const int m0 = (wid >> 2) * 32, n0 = (wid & 3) * 32;
    const u32 a_base  = (u32)__cvta_generic_to_shared(Ash);
    const u32 al_base = (u32)__cvta_generic_to_shared(Alos);
    const u32 w_base  = (u32)__cvta_generic_to_shared(Wsh);
    const u32 wl_base = (u32)__cvta_generic_to_shared(Wlos);
    const int a_i = lane & 7, a_sel = lane >> 3;
    const int a_row = ((a_sel & 1) ? 8 : 0) + a_i;
    const int a_kof = (a_sel & 2) ? 8 : 0;
    const int b_row = lane & 15;

    float acc[2][4][4];
#pragma unroll
    for (int mt = 0; mt < 2; mt++)
#pragma unroll
        for (int nt = 0; nt < 4; nt++)
#pragma unroll
            for (int q = 0; q < 4; q++) acc[mt][nt][q] = 0.f;

    if (MODE == 0) {
#pragma unroll
        for (int k0 = 0; k0 < DD; k0 += 16) {
            u32 ah[2][4], al[2][4], bh[4][2], bl[4][2];
#pragma unroll
            for (int mt = 0; mt < 2; mt++) {
                const u32 off = (u32)((m0 + mt * 16 + a_row) * (LDAB * 2) + (k0 + a_kof) * 2);
                ldsm4(ah[mt], a_base + off);
                ldsm4(al[mt], al_base + off);
            }
#pragma unroll
            for (int nt = 0; nt < 4; nt++) {
                const u32 off = (u32)((k0 + b_row) * (LDAB * 2) + (n0 + nt * 8) * 2);
                ldsm2t(bh[nt], w_base + off);
                ldsm2t(bl[nt], wl_base + off);
            }
#pragma unroll
            for (int mt = 0; mt < 2; mt++)
#pragma unroll
                for (int nt = 0; nt < 4; nt++) {
                    mma16816(acc[mt][nt], ah[mt], bh[nt]);
                    mma16816(acc[mt][nt], ah[mt], bl[nt]);
                    mma16816(acc[mt][nt], al[mt], bh[nt]);
                }
        }
    } else {
        u32 af[2][2][4], bf[2][4][2];
#pragma unroll
        for (int mt = 0; mt < 2; mt++)
            ldsm4(af[0][mt], a_base + (u32)((m0 + mt * 16 + a_row) * (LDAB * 2) + a_kof * 2));
#pragma unroll
        for (int nt = 0; nt < 4; nt++)
            ldsm2t(bf[0][nt], w_base + (u32)(b_row * (LDAB * 2) + (n0 + nt * 8) * 2));
#pragma unroll
        for (int ks = 0; ks < 8; ks++) {
            const int cur = ks & 1;
            if (ks < 7) {
                const int k1 = (ks + 1) * 16;
#pragma unroll
                for (int mt = 0; mt < 2; mt++)
                    ldsm4(af[cur ^ 1][mt], a_base + (u32)((m0 + mt * 16 + a_row) * (LDAB * 2) + (k1 + a_kof) * 2));
#pragma unroll
                for (int nt = 0; nt < 4; nt++)
                    ldsm2t(bf[cur ^ 1][nt], w_base + (u32)((k1 + b_row) * (LDAB * 2) + (n0 + nt * 8) * 2));
            }
#pragma unroll
            for (int mt = 0; mt < 2; mt++)
#pragma unroll
                for (int nt = 0; nt < 4; nt++)
                    mma16816(acc[mt][nt], af[cur][mt], bf[cur][nt]);
        }
    }

    __syncthreads();
    {
        const int g = lane >> 2, t = lane & 3;
#pragma unroll
        for (int mt = 0; mt < 2; mt++)
#pragma unroll
            for (int nt = 0; nt < 4; nt++) {
                const int row = m0 + mt * 16 + g;
                const int col = n0 + nt * 8 + 2 * t;
                *(float2*)(Csh + row * LDC + col)       = make_float2(acc[mt][nt][0], acc[mt][nt][1]);
                *(float2*)(Csh + (row + 8) * LDC + col) = make_float2(acc[mt][nt][2], acc[mt][nt][3]);
            }
    }
    __syncthreads();

    const float4 bias4 = *(const float4*)(bias + lane * 4);
    float af2 = 0.f;
    if (MODE == 2) af2 = __ldg(alpha_f);

#pragma unroll
    for (int i = 0; i < 8; i++) {
        const int lr = wid * 8 + i;
        const int r = row0 + lr;
        if (r >= NN) continue;
        float4 o = *(const float4*)(Csh + lr * LDC + lane * 4);
        if (MODE == 0) {
            o.x = siluf(o.x + bias4.x);
            o.y = siluf(o.y + bias4.y);
            o.z = siluf(o.z + bias4.z);
            o.w = siluf(o.w + bias4.w);
        } else {
            const float4 h1 = *(const float4*)(H1sh + lr * LDC + lane * 4);
            o.x = fmaf(af2, siluf(o.x + bias4.x), h1.x);
            o.y = fmaf(af2, siluf(o.y + bias4.y), h1.y);
            o.z = fmaf(af2, siluf(o.z + bias4.z), h1.z);
            o.w = fmaf(af2, siluf(o.w + bias4.w), h1.w);
        }
        *(float4*)(outf + (size_t)r * DD + lane * 4) = o;
    }
}

// ---------------- CSR gather v2: half-warp per edge, 16B loads ----------------
// lane = half*16 + hl; half-warp covers one full 256B row; acc[8] fp32 for cols [8*hl, 8*hl+8)
__global__ void __launch_bounds__(256) gather_kernel(
    const int* __restrict__ off, const int* __restrict__ eidx,
    const float* __restrict__ dinv, const __nv_bfloat16* __restrict__ c2b,
    __nv_bfloat16* __restrict__ aggb)
{
    const int n = blockIdx.x * 8 + (threadIdx.x >> 5);
    if (n >= NN) return;
    const int lane = threadIdx.x & 31;
    const int half = lane >> 4;
    const int hl   = lane & 15;
    const int s = __ldg(off + n), e = __ldg(off + n + 1);
    const float dn = __ldg(dinv + n);

    float acc[8];
    {   // self-loop term (half 0 only; combined at the end)
        uint4 u = *(const uint4*)(c2b + (size_t)n * DD + hl * 8);
        float f[8]; unp8(u, f);
        const float w0 = (half == 0) ? dn : 0.f;
#pragma unroll
        for (int i = 0; i < 8; i++) acc[i] = w0 * f[i];
    }

    for (int j0 = s; j0 < e; j0 += 32) {
        const int jn = min(32, e - j0);
        int eid = 0; float wv = 0.f;
        if (lane < jn) { eid = __ldg(eidx + j0 + lane); wv = __ldg(dinv + eid); }
        for (int t = 0; t < jn; t += 8) {   // 8 edges per step; 4 per half-warp
            int rr[4]; float ww[4]; uint4 vv[4];
#pragma unroll
            for (int q = 0; q < 4; q++) {
                const int idx = t + 2 * q + half;
                const int src = idx & 31;
                int  r = __shfl_sync(0xffffffffu, eid, src);
                float w = __shfl_sync(0xffffffffu, wv, src);
                const bool act = idx < jn;
                rr[q] = act ? r : 0;
                ww[q] = act ? w : 0.f;
            }
#pragma unroll
            for (int q = 0; q < 4; q++)
                vv[q] = __ldg((const uint4*)(c2b + (size_t)rr[q] * DD + hl * 8));
#pragma unroll
            for (int q = 0; q < 4; q++) {
                float f[8]; unp8(vv[q], f);
#pragma unroll
                for (int i = 0; i < 8; i++) acc[i] = fmaf(ww[q], f[i], acc[i]);
            }
        }
    }

    // combine halves (same hl -> same cols), scale, store (half 0)
#pragma unroll
    for (int i = 0; i < 8; i++) {
        acc[i] += __shfl_xor_sync(0xffffffffu, acc[i], 16);
        acc[i] *= dn;
    }
    if (half == 0) {
        uint4 o;
        o.x = pkbf2(acc[0], acc[1]);
        o.y = pkbf2(acc[2], acc[3]);
        o.z = pkbf2(acc[4], acc[5]);
        o.w = pkbf2(acc[6], acc[7]);
        *(uint4*)(aggb + (size_t)n * DD + hl * 8) = o;
    }
}

// ---------------- final: logits + log_softmax ----------------
__global__ void __launch_bounds__(128) final_kernel(
    const float* __restrict__ h, const float* __restrict__ Wf,
    const float* __restrict__ fb, float* __restrict__ out)
{
    __shared__ float Wsh[DD * CC];
    __shared__ float bsh[CC];
    __shared__ float rowbuf[4][DD];
    const int tid = threadIdx.x;
    for (int i = tid; i < DD * CC; i += 128) Wsh[i] = Wf[i];
    if (tid < CC) bsh[tid] = fb[tid];
    __syncthreads();

    const int wid = tid >> 5, lane = tid & 31;
    const int rbase = blockIdx.x * 32 + wid * 8;
    const bool has1 = (lane < CC - 32);

    for (int ri = 0; ri < 8; ri++) {
        const int r = rbase + ri;
        if (r >= NN) return;
        float4 v = *(const float4*)(h + (size_t)r * DD + lane * 4);
        *(float4*)(&rowbuf[wid][lane * 4]) = v;
        __syncwarp();
        float acc0 = bsh[lane];
        float acc1 = has1 ? bsh[32 + lane] : 0.f;
#pragma unroll 4
        for (int k = 0; k < DD; k++) {
            float hv = rowbuf[wid][k];
            acc0 = fmaf(hv, Wsh[k * CC + lane], acc0);
            if (has1) acc1 = fmaf(hv, Wsh[k * CC + 32 + lane], acc1);
        }
        float m = has1 ? fmaxf(acc0, acc1) : acc0;
#pragma unroll
        for (int o = 16; o > 0; o >>= 1) m = fmaxf(m, __shfl_xor_sync(0xffffffffu, m, o));
        float s = expf(acc0 - m) + (has1 ? expf(acc1 - m) : 0.f);
#pragma unroll
        for (int o = 16; o > 0; o >>= 1) s += __shfl_xor_sync(0xffffffffu, s, o);
        const float ls = logf(s);
        out[(size_t)r * CC + lane] = acc0 - m - ls;
        if (has1) out[(size_t)r * CC + 32 + lane] = acc1 - m - ls;
        __syncwarp();
    }
}

// ---------------- launch ----------------
extern "C" void kernel_launch(void* const* d_in, const int* in_sizes, int n_in,
                              void* d_out, int out_size)
{
    const float* x       = (const float*)d_in[0];
    const int*   ei      = (const int*)  d_in[1];
    const float* start_W = (const float*)d_in[2];
    const float* start_b = (const float*)d_in[3];
    const float* ln1_g   = (const float*)d_in[4];
    const float* ln1_b   = (const float*)d_in[5];
    const float* convW   = (const float*)d_in[6];
    const float* convB   = (const float*)d_in[7];
    const float* alpha_g = (const float*)d_in[8];
    const float* ln2_g   = (const float*)d_in[9];
    const float* ln2_b   = (const float*)d_in[10];
    const float* ffwW    = (const float*)d_in[11];
    const float* ffwB    = (const float*)d_in[12];
    const float* alpha_f = (const float*)d_in[13];
    const float* final_W = (const float*)d_in[14];
    const float* final_b = (const float*)d_in[15];
    float* out = (float*)d_out;

    float *h, *dinv;
    __nv_bfloat16 *c2b, *aggb, *wb, *w0hi, *w0lo;
    int *counts, *off, *cur, *eidx, *part;
    cudaGetSymbolAddress((void**)&h, g_h);
    cudaGetSymbolAddress((void**)&c2b, g_c2b);
    cudaGetSymbolAddress((void**)&aggb, g_aggb);
    cudaGetSymbolAddress((void**)&wb, g_wb);
    cudaGetSymbolAddress((void**)&w0hi, g_w0hi);
    cudaGetSymbolAddress((void**)&w0lo, g_w0lo);
    cudaGetSymbolAddress((void**)&dinv, g_dinv);
    cudaGetSymbolAddress((void**)&counts, g_counts);
    cudaGetSymbolAddress((void**)&off, g_off);
    cudaGetSymbolAddress((void**)&cur, g_cur);
    cudaGetSymbolAddress((void**)&eidx, g_eidx);
    cudaGetSymbolAddress((void**)&part, g_part);

    const int* rowi = ei;
    const int* coli = ei + NE;

    cudaFuncSetAttribute(gemm_bf16_kernel<0>, cudaFuncAttributeMaxDynamicSharedMemorySize, SM_M0);
    cudaFuncSetAttribute(gemm_bf16_kernel<2>, cudaFuncAttributeMaxDynamicSharedMemorySize, SM_M2);
    cudaFuncSetAttribute(gemm1_kernel, cudaFuncAttributeMaxDynamicSharedMemorySize, SM_G1);

    const int GB = (NN + 63) / 64;
    const int G1 = (NN + 127) / 128;
    const int NW = DD * DD + 2 * NL * DD * DD;

    // gemm1 at capture slot #4 (control: expect ~35.2us)
    convert_w_kernel<<<(NW + 255) / 256, 256>>>(start_W, convW, ffwW, w0hi, w0lo, wb);   // 1
    gemm_bf16_kernel<0><<<GB, 256, SM_M0>>>(x, w0hi, w0lo, start_b,                       // 2
                                            nullptr, nullptr, nullptr, nullptr,
                                            nullptr, nullptr, h);
    zero_counts_kernel<<<(NN + 255) / 256, 256>>>(counts);                                // 3
    gemm1_kernel<<<G1, 256, SM_G1>>>(h, wb, ln1_g, ln1_b, c2b);                           // 4 (capture)
    count_kernel<<<(NE + 255) / 256, 256>>>(coli, counts);                                // 5
    scan_block_kernel<<<NB_SCAN, 1024>>>(counts, off, part);
    scan_part_kernel<<<1, 32>>>(part, off);
    add_carry_kernel<<<(NN + 255) / 256, 256>>>(counts, off, part, cur, dinv);
    fill_kernel<<<(NE + 255) / 256, 256>>>(rowi, coli, cur, eidx);

    for (int i = 0; i < NL; i++) {
        if (i > 0)
            gemm1_kernel<<<G1, 256, SM_G1>>>(h, wb + (size_t)i * DD * DD,
                                             ln1_g + i * DD, ln1_b + i * DD, c2b);
        gather_kernel<<<(NN + 7) / 8, 256>>>(off, eidx, dinv, c2b, aggb);
        gemm_bf16_kernel<2><<<GB, 256, SM_M2>>>(h, wb + (size_t)(NL + i) * DD * DD, nullptr,
                                                ffwB + i * DD,
                                                ln2_g + i * DD, ln2_b + i * DD,
                                                aggb, convB + i * DD,
                                                alpha_g + i, alpha_f + i, h);
    }

    final_kernel<<<(NN + 31) / 32, 128>>>(h, final_W, final_b, out);
}

// round 15
// speedup vs baseline: 1.0364x; 1.0143x over previous
#include <cuda_runtime.h>
#include <cuda_bf16.h>
#include <math.h>

#define NN 100000
#define NE 1600000
#define DD 128
#define CC 40
#define NL 3
#define NB_SCAN 98

__device__ float          g_h[(size_t)NN * DD];
__device__ __nv_bfloat16  g_c2b[(size_t)NN * DD];
__device__ __nv_bfloat16  g_aggb[(size_t)NN * DD];
__device__ __nv_bfloat16  g_wb[6 * DD * DD];
__device__ __nv_bfloat16  g_w0hi[DD * DD];
__device__ __nv_bfloat16  g_w0lo[DD * DD];
__device__ float g_dinv[NN];
__device__ int g_counts[NN], g_off[NN + 1], g_cur[NN], g_eidx[NE], g_part[128];

typedef unsigned long long u64;
typedef unsigned int u32;

__device__ __forceinline__ float siluf(float x) { return x / (1.0f + expf(-x)); }

__device__ __forceinline__ float warp_sum(float v) {
#pragma unroll
    for (int o = 16; o > 0; o >>= 1) v += __shfl_xor_sync(0xffffffffu, v, o);
    return v;
}
__device__ __forceinline__ float4 ldb4(const __nv_bfloat16* p) {
    uint2 u = *(const uint2*)p;
    __nv_bfloat162 a = *reinterpret_cast<const __nv_bfloat162*>(&u.x);
    __nv_bfloat162 b = *reinterpret_cast<const __nv_bfloat162*>(&u.y);
    float2 fa = __bfloat1622float2(a), fb = __bfloat1622float2(b);
    return make_float4(fa.x, fa.y, fb.x, fb.y);
}
__device__ __forceinline__ u32 pkbf2(float a, float b) {
    __nv_bfloat162 t = __floats2bfloat162_rn(a, b);
    return *reinterpret_cast<u32*>(&t);
}
__device__ __forceinline__ void unp8(uint4 u, float* o) {
    __nv_bfloat162 p0 = *reinterpret_cast<__nv_bfloat162*>(&u.x);
    __nv_bfloat162 p1 = *reinterpret_cast<__nv_bfloat162*>(&u.y);
    __nv_bfloat162 p2 = *reinterpret_cast<__nv_bfloat162*>(&u.z);
    __nv_bfloat162 p3 = *reinterpret_cast<__nv_bfloat162*>(&u.w);
    float2 f0 = __bfloat1622float2(p0), f1 = __bfloat1622float2(p1);
    float2 f2 = __bfloat1622float2(p2), f3 = __bfloat1622float2(p3);
    o[0] = f0.x; o[1] = f0.y; o[2] = f1.x; o[3] = f1.y;
    o[4] = f2.x; o[5] = f2.y; o[6] = f3.x; o[7] = f3.y;
}
__device__ __forceinline__ void ldsm4(u32* f, u32 addr) {
    asm volatile("ldmatrix.sync.aligned.m8n8.x4.shared.b16 {%0,%1,%2,%3}, [%4];"
                 : "=r"(f[0]), "=r"(f[1]), "=r"(f[2]), "=r"(f[3]) : "r"(addr));
}
__device__ __forceinline__ void ldsm2t(u32* f, u32 addr) {
    asm volatile("ldmatrix.sync.aligned.m8n8.x2.trans.shared.b16 {%0,%1}, [%2];"
                 : "=r"(f[0]), "=r"(f[1]) : "r"(addr));
}
__device__ __forceinline__ void mma16816(float* c, const u32* a, const u32* b) {
    asm volatile("mma.sync.aligned.m16n8k16.row.col.f32.bf16.bf16.f32 "
                 "{%0,%1,%2,%3}, {%4,%5,%6,%7}, {%8,%9}, {%0,%1,%2,%3};"
                 : "+f"(c[0]), "+f"(c[1]), "+f"(c[2]), "+f"(c[3])
                 : "r"(a[0]), "r"(a[1]), "r"(a[2]), "r"(a[3]), "r"(b[0]), "r"(b[1]));
}

// ---------------- weight conversion ----------------
__global__ void convert_w_kernel(const float* __restrict__ startW,
                                 const float* __restrict__ convW,
                                 const float* __restrict__ ffwW,
                                 __nv_bfloat16* __restrict__ w0hi,
                                 __nv_bfloat16* __restrict__ w0lo,
                                 __nv_bfloat16* __restrict__ wb) {
    const int i = blockIdx.x * blockDim.x + threadIdx.x;
    const int s = DD * DD, per = NL * DD * DD;
    if (i < s) {
        float v = startW[i];
        __nv_bfloat16 hi = __float2bfloat16(v);
        w0hi[i] = hi;
        w0lo[i] = __float2bfloat16(v - __bfloat162float(hi));
    } else if (i < s + per) {
        wb[i - s] = __float2bfloat16(convW[i - s]);
    } else if (i < s + 2 * per) {
        wb[i - s] = __float2bfloat16(ffwW[i - s - per]);
    }
}

// ---------------- CSR build ----------------
__global__ void zero_counts_kernel(int* c) { int i = blockIdx.x * blockDim.x + threadIdx.x; if (i < NN) c[i] = 0; }
__global__ void count_kernel(const int* __restrict__ col, int* __restrict__ c) {
    int e = blockIdx.x * blockDim.x + threadIdx.x; if (e < NE) atomicAdd(&c[col[e]], 1);
}
__global__ void __launch_bounds__(1024) scan_block_kernel(const int* __restrict__ counts,
                                                          int* __restrict__ off, int* __restrict__ part) {
    __shared__ int wsum[32];
    const int t = threadIdx.x, lane = t & 31, w = t >> 5;
    const int i = blockIdx.x * 1024 + t;
    const int v = (i < NN) ? counts[i] : 0;
    int x = v;
#pragma unroll
    for (int o = 1; o < 32; o <<= 1) { int y = __shfl_up_sync(0xffffffffu, x, o); if (lane >= o) x += y; }
    if (lane == 31) wsum[w] = x;
    __syncthreads();
    if (w == 0) {
        int y = wsum[lane];
#pragma unroll
        for (int o = 1; o < 32; o <<= 1) { int z = __shfl_up_sync(0xffffffffu, y, o); if (lane >= o) y += z; }
        wsum[lane] = y;
    }
    __syncthreads();
    const int incl = x + (w > 0 ? wsum[w - 1] : 0);
    if (i < NN) off[i + 1] = incl;
    if (t == 1023) part[blockIdx.x] = incl;
}
__global__ void scan_part_kernel(int* __restrict__ part, int* __restrict__ off) {
    const int lane = threadIdx.x;
    int carry = 0;
    for (int base = 0; base < 128; base += 32) {
        const int idx = base + lane;
        const int v = (idx < NB_SCAN) ? part[idx] : 0;
        int x = v;
#pragma unroll
        for (int o = 1; o < 32; o <<= 1) { int y = __shfl_up_sync(0xffffffffu, x, o); if (lane >= o) x += y; }
        if (idx < NB_SCAN) part[idx] = carry + x - v;
        carry += __shfl_sync(0xffffffffu, x, 31);
    }
    if (lane == 0) off[0] = 0;
}
__global__ void add_carry_kernel(const int* __restrict__ counts, int* __restrict__ off,
                                 const int* __restrict__ part, int* __restrict__ cur,
                                 float* __restrict__ dinv) {
    const int i = blockIdx.x * blockDim.x + threadIdx.x;
    if (i >= NN) return;
    const int c = counts[i];
    const int o = off[i + 1] + part[i >> 10];
    off[i + 1] = o; cur[i] = o - c;
    dinv[i] = rsqrtf((float)(c + 1));
}
__global__ void fill_kernel(const int* __restrict__ rowi, const int* __restrict__ coli,
                            int* __restrict__ cur, int* __restrict__ eidx) {
    int e = blockIdx.x * blockDim.x + threadIdx.x;
    if (e < NE) { int p = atomicAdd(&cur[coli[e]], 1); eidx[p] = rowi[e]; }
}

#define LDAB 136
#define LDC  132

// ---------------- conv GEMM: 128x128 block (measured 35.1us) ----------------
#define SM_G1 69632
__global__ void __launch_bounds__(256, 2) gemm1_kernel(
    const float* __restrict__ in, const __nv_bfloat16* __restrict__ Wb,
    const float* __restrict__ lng, const float* __restrict__ lnb,
    __nv_bfloat16* __restrict__ outb)
{
    extern __shared__ __align__(16) char smem[];
    __nv_bfloat16* Wsh = (__nv_bfloat16*)(smem);
    __nv_bfloat16* Ash = (__nv_bfloat16*)(smem + 34816);
    const int tid = threadIdx.x, wid = tid >> 5, lane = tid & 31;
    const int row0 = blockIdx.x * 128;

    {
        const int r = tid >> 1, half = tid & 1;
        const uint4* src = (const uint4*)(Wb + (size_t)r * DD + half * 64);
        uint4* dst = (uint4*)(Wsh + r * LDAB + half * 64);
#pragma unroll
        for (int j = 0; j < 8; j++) dst[j] = src[j];
    }
    {
        const float4 g4 = *(const float4*)(lng + lane * 4);
        const float4 b4 = *(const float4*)(lnb + lane * 4);
#pragma unroll
        for (int i = 0; i < 16; i++) {
            const int lr = wid * 16 + i;
            const int r = row0 + lr;
            float4 v = (r < NN) ? *(const float4*)(in + (size_t)r * DD + lane * 4)
                                : make_float4(0.f, 0.f, 0.f, 0.f);
            float s1 = warp_sum(v.x + v.y + v.z + v.w);
            float s2 = warp_sum(v.x * v.x + v.y * v.y + v.z * v.z + v.w * v.w);
            float mu  = s1 * (1.0f / 128.0f);
            float var = fmaxf(s2 * (1.0f / 128.0f) - mu * mu, 0.0f);
            float rs  = rsqrtf(var + 1e-5f);
            uint2 p;
            p.x = pkbf2((v.x - mu) * rs * g4.x + b4.x, (v.y - mu) * rs * g4.y + b4.y);
            p.y = pkbf2((v.z - mu) * rs * g4.z + b4.z, (v.w - mu) * rs * g4.w + b4.w);
            *(uint2*)(Ash + lr * LDAB + lane * 4) = p;
        }
    }
    __syncthreads();

    const int m0 = (wid >> 1) * 32, n0 = (wid & 1) * 64;
    const u32 a_base = (u32)__cvta_generic_to_shared(Ash);
    const u32 w_base = (u32)__cvta_generic_to_shared(Wsh);
    const int a_i = lane & 7, a_sel = lane >> 3;
    const int a_row = ((a_sel & 1) ? 8 : 0) + a_i;
    const int a_kof = (a_sel & 2) ? 8 : 0;
    const int b_row = lane & 15;

    float acc[2][8][4];
#pragma unroll
    for (int mt = 0; mt < 2; mt++)
#pragma unroll
        for (int nt = 0; nt < 8; nt++)
#pragma unroll
            for (int q = 0; q < 4; q++) acc[mt][nt][q] = 0.f;

#pragma unroll
    for (int k0 = 0; k0 < DD; k0 += 16) {
        u32 af[2][4], bf[8][2];
#pragma unroll
        for (int mt = 0; mt < 2; mt++)
            ldsm4(af[mt], a_base + (u32)((m0 + mt * 16 + a_row) * (LDAB * 2) + (k0 + a_kof) * 2));
#pragma unroll
        for (int nt = 0; nt < 8; nt++)
            ldsm2t(bf[nt], w_base + (u32)((k0 + b_row) * (LDAB * 2) + (n0 + nt * 8) * 2));
#pragma unroll
        for (int mt = 0; mt < 2; mt++)
#pragma unroll
            for (int nt = 0; nt < 8; nt++)
                mma16816(acc[mt][nt], af[mt], bf[nt]);
    }

    const int g = lane >> 2, t = lane & 3;
#pragma unroll
    for (int mt = 0; mt < 2; mt++) {
        const int r0 = row0 + m0 + mt * 16 + g;
        const int r1 = r0 + 8;
#pragma unroll
        for (int nt = 0; nt < 8; nt++) {
            const int col = n0 + nt * 8 + 2 * t;
            if (r0 < NN) *(u32*)(outb + (size_t)r0 * DD + col) = pkbf2(acc[mt][nt][0], acc[mt][nt][1]);
            if (r1 < NN) *(u32*)(outb + (size_t)r1 * DD + col) = pkbf2(acc[mt][nt][2], acc[mt][nt][3]);
        }
    }
}

// ---------------- start GEMM: 128x128 block, split-bf16 (3 MMA groups) ----------------
// Whi[0,34816) Wlo[34816,69632) Ahi[69632,104448) Alo[104448,139264); Csh overlays Whi/Wlo
#define SM_M0 139264
__global__ void __launch_bounds__(256, 1) gemm0_kernel(
    const float* __restrict__ in,
    const __nv_bfloat16* __restrict__ Whi, const __nv_bfloat16* __restrict__ Wlo,
    const float* __restrict__ bias, float* __restrict__ outf)
{
    extern __shared__ __align__(16) char smem[];
    __nv_bfloat16* Wsh  = (__nv_bfloat16*)(smem);
    __nv_bfloat16* Wlos = (__nv_bfloat16*)(smem + 34816);
    __nv_bfloat16* Ash  = (__nv_bfloat16*)(smem + 69632);
    __nv_bfloat16* Alos = (__nv_bfloat16*)(smem + 104448);
    float*         Csh  = (float*)(smem);

    const int tid = threadIdx.x, wid = tid >> 5, lane = tid & 31;
    const int row0 = blockIdx.x * 128;

    {
        const int r = tid >> 1, half = tid & 1;
        const uint4* s1 = (const uint4*)(Whi + (size_t)r * DD + half * 64);
        uint4* d1 = (uint4*)(Wsh + r * LDAB + half * 64);
#pragma unroll
        for (int j = 0; j < 8; j++) d1[j] = s1[j];
        const uint4* s2 = (const uint4*)(Wlo + (size_t)r * DD + half * 64);
        uint4* d2 = (uint4*)(Wlos + r * LDAB + half * 64);
#pragma unroll
        for (int j = 0; j < 8; j++) d2[j] = s2[j];
    }
#pragma unroll
    for (int i = 0; i < 16; i++) {
        const int lr = wid * 16 + i;
        const int r = row0 + lr;
        float4 v = (r < NN) ? *(const float4*)(in + (size_t)r * DD + lane * 4)
                            : make_float4(0.f, 0.f, 0.f, 0.f);
        __nv_bfloat16 hx = __float2bfloat16(v.x), hy = __float2bfloat16(v.y);
        __nv_bfloat16 hz = __float2bfloat16(v.z), hw = __float2bfloat16(v.w);
        uint2 phi;
        phi.x = pkbf2(__bfloat162float(hx), __bfloat162float(hy));
        phi.y = pkbf2(__bfloat162float(hz), __bfloat162float(hw));
        *(uint2*)(Ash + lr * LDAB + lane * 4) = phi;
        uint2 plo;
        plo.x = pkbf2(v.x - __bfloat162float(hx), v.y - __bfloat162float(hy));
        plo.y = pkbf2(v.z - __bfloat162float(hz), v.w - __bfloat162float(hw));
        *(uint2*)(Alos + lr * LDAB + lane * 4) = plo;
    }
    __syncthreads();

    const int m0 = (wid >> 1) * 32, n0 = (wid & 1) * 64;
    const u32 a_base  = (u32)__cvta_generic_to_shared(Ash);
    const u32 al_base = (u32)__cvta_generic_to_shared(Alos);
    const u32 w_base  = (u32)__cvta_generic_to_shared(Wsh);
    const u32 wl_base = (u32)__cvta_generic_to_shared(Wlos);
    const int a_i = lane & 7, a_sel = lane >> 3;
    const int a_row = ((a_sel & 1) ? 8 : 0) + a_i;
    const int a_kof = (a_sel & 2) ? 8 : 0;
    const int b_row = lane & 15;

    float acc[2][8][4];
#pragma unroll
    for (int mt = 0; mt < 2; mt++)
#pragma unroll
        for (int nt = 0; nt < 8; nt++)
#pragma unroll
            for (int q = 0; q < 4; q++) acc[mt][nt][q] = 0.f;

#pragma unroll
    for (int k0 = 0; k0 < DD; k0 += 16) {
        u32 ah[2][4], al[2][4], bh[8][2], bl[8][2];
#pragma unroll
        for (int mt = 0; mt < 2; mt++) {
            const u32 off = (u32)((m0 + mt * 16 + a_row) * (LDAB * 2) + (k0 + a_kof) * 2);
            ldsm4(ah[mt], a_base + off);
            ldsm4(al[mt], al_base + off);
        }
#pragma unroll
        for (int nt = 0; nt < 8; nt++) {
            const u32 off = (u32)((k0 + b_row) * (LDAB * 2) + (n0 + nt * 8) * 2);
            ldsm2t(bh[nt], w_base + off);
            ldsm2t(bl[nt], wl_base + off);
        }
#pragma unroll
        for (int mt = 0; mt < 2; mt++)
#pragma unroll
            for (int nt = 0; nt < 8; nt++) {
                mma16816(acc[mt][nt], ah[mt], bh[nt]);
                mma16816(acc[mt][nt], ah[mt], bl[nt]);
                mma16816(acc[mt][nt], al[mt], bh[nt]);
            }
    }

    __syncthreads();   // done reading W tiles; overlay C
    {
        const int g = lane >> 2, t = lane & 3;
#pragma unroll
        for (int mt = 0; mt < 2; mt++)
#pragma unroll
            for (int nt = 0; nt < 8; nt++) {
                const int row = m0 + mt * 16 + g;
                const int col = n0 + nt * 8 + 2 * t;
                *(float2*)(Csh + row * LDC + col)       = make_float2(acc[mt][nt][0], acc[mt][nt][1]);
                *(float2*)(Csh + (row + 8) * LDC + col) = make_float2(acc[mt][nt][2], acc[mt][nt][3]);
            }
    }
    __syncthreads();

    const float4 bias4 = *(const float4*)(bias + lane * 4);
#pragma unroll
    for (int i = 0; i < 16; i++) {
        const int lr = wid * 16 + i;
        const int r = row0 + lr;
        if (r >= NN) continue;
        float4 o = *(const float4*)(Csh + lr * LDC + lane * 4);
        o.x = siluf(o.x + bias4.x);
        o.y = siluf(o.y + bias4.y);
        o.z = siluf(o.z + bias4.z);
        o.w = siluf(o.w + bias4.w);
        *(float4*)(outf + (size_t)r * DD + lane * 4) = o;
    }
}

// ---------------- ffn GEMM (MODE 2) — R8-proven 64-row ----------------
#define SM_M2 86016
__global__ void __launch_bounds__(256, 2) gemm2_kernel(
    const float* __restrict__ in,
    const __nv_bfloat16* __restrict__ Wb,
    const float* __restrict__ bias,
    const float* __restrict__ lng,
    const float* __restrict__ lnb,
    const __nv_bfloat16* __restrict__ aggb,
    const float* __restrict__ convB,
    const float* __restrict__ alpha_g,
    const float* __restrict__ alpha_f,
    float* __restrict__ outf)
{
    extern __shared__ __align__(16) char smem[];
    __nv_bfloat16* Wsh  = (__nv_bfloat16*)(smem);
    __nv_bfloat16* Ash  = (__nv_bfloat16*)(smem + 34816);
    float*         H1sh = (float*)(smem + 52224);
    float*         Csh  = (float*)(smem);

    const int tid = threadIdx.x, wid = tid >> 5, lane = tid & 31;
    const int row0 = blockIdx.x * 64;
    const float ag = __ldg(alpha_g);

    {
        const int r = tid >> 1, half = tid & 1;
        const uint4* src = (const uint4*)(Wb + (size_t)r * DD + half * 64);
        uint4* dst = (uint4*)(Wsh + r * LDAB + half * 64);
#pragma unroll
        for (int j = 0; j < 8; j++) dst[j] = src[j];
    }
    {
        const float4 g4  = *(const float4*)(lng + lane * 4);
        const float4 b4  = *(const float4*)(lnb + lane * 4);
        const float4 cb4 = *(const float4*)(convB + lane * 4);
#pragma unroll
        for (int i = 0; i < 8; i++) {
            const int lr = wid * 8 + i;
            const int r = row0 + lr;
            float4 v = make_float4(0.f, 0.f, 0.f, 0.f);
            float4 av = make_float4(0.f, 0.f, 0.f, 0.f);
            if (r < NN) {
                v  = *(const float4*)(in + (size_t)r * DD + lane * 4);
                av = ldb4(aggb + (size_t)r * DD + lane * 4);
            }
            v.x = fmaf(ag, siluf(av.x + cb4.x), v.x);
            v.y = fmaf(ag, siluf(av.y + cb4.y), v.y);
            v.z = fmaf(ag, siluf(av.z + cb4.z), v.z);
            v.w = fmaf(ag, siluf(av.w + cb4.w), v.w);
            *(float4*)(H1sh + lr * LDC + lane * 4) = v;
            float s1 = warp_sum(v.x + v.y + v.z + v.w);
            float s2 = warp_sum(v.x * v.x + v.y * v.y + v.z * v.z + v.w * v.w);
            float mu  = s1 * (1.0f / 128.0f);
            float var = fmaxf(s2 * (1.0f / 128.0f) - mu * mu, 0.0f);
            float rs  = rsqrtf(var + 1e-5f);
            uint2 p;
            p.x = pkbf2((v.x - mu) * rs * g4.x + b4.x, (v.y - mu) * rs * g4.y + b4.y);
            p.y = pkbf2((v.z - mu) * rs * g4.z + b4.z, (v.w - mu) * rs * g4.w + b4.w);
            *(uint2*)(Ash + lr * LDAB + lane * 4) = p;
        }
    }
    __syncthreads();

    const int m0 = (wid >> 2) * 32, n0 = (wid & 3) * 32;
    const u32 a_base = (u32)__cvta_generic_to_shared(Ash);
    const u32 w_base = (u32)__cvta_generic_to_shared(Wsh);
    const int a_i = lane & 7, a_sel = lane >> 3;
    const int a_row = ((a_sel & 1) ? 8 : 0) + a_i;
    const int a_kof = (a_sel & 2) ? 8 : 0;
    const int b_row = lane & 15;

    float acc[2][4][4];
#pragma unroll
    for (int mt = 0; mt < 2; mt++)
#pragma unroll
        for (int nt = 0; nt < 4; nt++)
#pragma unroll
            for (int q = 0; q < 4; q++) acc[mt][nt][q] = 0.f;

    u32 af[2][2][4], bf[2][4][2];
#pragma unroll
    for (int mt = 0; mt < 2; mt++)
        ldsm4(af[0][mt], a_base + (u32)((m0 + mt * 16 + a_row) * (LDAB * 2) + a_kof * 2));
#pragma unroll
    for (int nt = 0; nt < 4; nt++)
        ldsm2t(bf[0][nt], w_base + (u32)(b_row * (LDAB * 2) + (n0 + nt * 8) * 2));
#pragma unroll
    for (int ks = 0; ks < 8; ks++) {
        const int cur = ks & 1;
        if (ks < 7) {
            const int k1 = (ks + 1) * 16;
#pragma unroll
            for (int mt = 0; mt < 2; mt++)
                ldsm4(af[cur ^ 1][mt], a_base + (u32)((m0 + mt * 16 + a_row) * (LDAB * 2) + (k1 + a_kof) * 2));
#pragma unroll
            for (int nt = 0; nt < 4; nt++)
                ldsm2t(bf[cur ^ 1][nt], w_base + (u32)((k1 + b_row) * (LDAB * 2) + (n0 + nt * 8) * 2));
        }
#pragma unroll
        for (int mt = 0; mt < 2; mt++)
#pragma unroll
            for (int nt = 0; nt < 4; nt++)
                mma16816(acc[mt][nt], af[cur][mt], bf[cur][nt]);
    }

    __syncthreads();
    {
        const int g = lane >> 2, t = lane & 3;
#pragma unroll
        for (int mt = 0; mt < 2; mt++)
#pragma unroll
            for (int nt = 0; nt < 4; nt++) {
                const int row = m0 + mt * 16 + g;
                const int col = n0 + nt * 8 + 2 * t;
                *(float2*)(Csh + row * LDC + col)       = make_float2(acc[mt][nt][0], acc[mt][nt][1]);
                *(float2*)(Csh + (row + 8) * LDC + col) = make_float2(acc[mt][nt][2], acc[mt][nt][3]);
            }
    }
    __syncthreads();

    const float4 bias4 = *(const float4*)(bias + lane * 4);
    const float af2 = __ldg(alpha_f);
#pragma unroll
    for (int i = 0; i < 8; i++) {
        const int lr = wid * 8 + i;
        const int r = row0 + lr;
        if (r >= NN) continue;
        float4 o = *(const float4*)(Csh + lr * LDC + lane * 4);
        const float4 h1 = *(const float4*)(H1sh + lr * LDC + lane * 4);
        o.x = fmaf(af2, siluf(o.x + bias4.x), h1.x);
        o.y = fmaf(af2, siluf(o.y + bias4.y), h1.y);
        o.z = fmaf(af2, siluf(o.z + bias4.z), h1.z);
        o.w = fmaf(af2, siluf(o.w + bias4.w), h1.w);
        *(float4*)(outf + (size_t)r * DD + lane * 4) = o;
    }
}

// ---------------- CSR gather v2: half-warp per edge, 16B loads (measured best) ----------------
__global__ void __launch_bounds__(256) gather_kernel(
    const int* __restrict__ off, const int* __restrict__ eidx,
    const float* __restrict__ dinv, const __nv_bfloat16* __restrict__ c2b,
    __nv_bfloat16* __restrict__ aggb)
{
    const int n = blockIdx.x * 8 + (threadIdx.x >> 5);
    if (n >= NN) return;
    const int lane = threadIdx.x & 31;
    const int half = lane >> 4;
    const int hl   = lane & 15;
    const int s = __ldg(off + n), e = __ldg(off + n + 1);
    const float dn = __ldg(dinv + n);

    float acc[8];
    {
        uint4 u = *(const uint4*)(c2b + (size_t)n * DD + hl * 8);
        float f[8]; unp8(u, f);
        const float w0 = (half == 0) ? dn : 0.f;
#pragma unroll
        for (int i = 0; i < 8; i++) acc[i] = w0 * f[i];
    }

    for (int j0 = s; j0 < e; j0 += 32) {
        const int jn = min(32, e - j0);
        int eid = 0; float wv = 0.f;
        if (lane < jn) { eid = __ldg(eidx + j0 + lane); wv = __ldg(dinv + eid); }
        for (int t = 0; t < jn; t += 8) {
            int rr[4]; float ww[4]; uint4 vv[4];
#pragma unroll
            for (int q = 0; q < 4; q++) {
                const int idx = t + 2 * q + half;
                const int src = idx & 31;
                int  r = __shfl_sync(0xffffffffu, eid, src);
                float w = __shfl_sync(0xffffffffu, wv, src);
                const bool act = idx < jn;
                rr[q] = act ? r : 0;
                ww[q] = act ? w : 0.f;
            }
#pragma unroll
            for (int q = 0; q < 4; q++)
                vv[q] = __ldg((const uint4*)(c2b + (size_t)rr[q] * DD + hl * 8));
#pragma unroll
            for (int q = 0; q < 4; q++) {
                float f[8]; unp8(vv[q], f);
#pragma unroll
                for (int i = 0; i < 8; i++) acc[i] = fmaf(ww[q], f[i], acc[i]);
            }
        }
    }

#pragma unroll
    for (int i = 0; i < 8; i++) {
        acc[i] += __shfl_xor_sync(0xffffffffu, acc[i], 16);
        acc[i] *= dn;
    }
    if (half == 0) {
        uint4 o;
        o.x = pkbf2(acc[0], acc[1]);
        o.y = pkbf2(acc[2], acc[3]);
        o.z = pkbf2(acc[4], acc[5]);
        o.w = pkbf2(acc[6], acc[7]);
        *(uint4*)(aggb + (size_t)n * DD + hl * 8) = o;
    }
}

// ---------------- final: logits + log_softmax ----------------
__global__ void __launch_bounds__(128) final_kernel(
    const float* __restrict__ h, const float* __restrict__ Wf,
    const float* __restrict__ fb, float* __restrict__ out)
{
    __shared__ float Wsh[DD * CC];
    __shared__ float bsh[CC];
    __shared__ float rowbuf[4][DD];
    const int tid = threadIdx.x;
    for (int i = tid; i < DD * CC; i += 128) Wsh[i] = Wf[i];
    if (tid < CC) bsh[tid] = fb[tid];
    __syncthreads();

    const int wid = tid >> 5, lane = tid & 31;
    const int rbase = blockIdx.x * 32 + wid * 8;
    const bool has1 = (lane < CC - 32);

    for (int ri = 0; ri < 8; ri++) {
        const int r = rbase + ri;
        if (r >= NN) return;
        float4 v = *(const float4*)(h + (size_t)r * DD + lane * 4);
        *(float4*)(&rowbuf[wid][lane * 4]) = v;
        __syncwarp();
        float acc0 = bsh[lane];
        float acc1 = has1 ? bsh[32 + lane] : 0.f;
#pragma unroll 4
        for (int k = 0; k < DD; k++) {
            float hv = rowbuf[wid][k];
            acc0 = fmaf(hv, Wsh[k * CC + lane], acc0);
            if (has1) acc1 = fmaf(hv, Wsh[k * CC + 32 + lane], acc1);
        }
        float m = has1 ? fmaxf(acc0, acc1) : acc0;
#pragma unroll
        for (int o = 16; o > 0; o >>= 1) m = fmaxf(m, __shfl_xor_sync(0xffffffffu, m, o));
        float s = expf(acc0 - m) + (has1 ? expf(acc1 - m) : 0.f);
#pragma unroll
        for (int o = 16; o > 0; o >>= 1) s += __shfl_xor_sync(0xffffffffu, s, o);
        const float ls = logf(s);
        out[(size_t)r * CC + lane] = acc0 - m - ls;
        if (has1) out[(size_t)r * CC + 32 + lane] = acc1 - m - ls;
        __syncwarp();
    }
}

// ---------------- launch ----------------
extern "C" void kernel_launch(void* const* d_in, const int* in_sizes, int n_in,
                              void* d_out, int out_size)
{
    const float* x       = (const float*)d_in[0];
    const int*   ei      = (const int*)  d_in[1];
    const float* start_W = (const float*)d_in[2];
    const float* start_b = (const float*)d_in[3];
    const float* ln1_g   = (const float*)d_in[4];
    const float* ln1_b   = (const float*)d_in[5];
    const float* convW   = (const float*)d_in[6];
    const float* convB   = (const float*)d_in[7];
    const float* alpha_g = (const float*)d_in[8];
    const float* ln2_g   = (const float*)d_in[9];
    const float* ln2_b   = (const float*)d_in[10];
    const float* ffwW    = (const float*)d_in[11];
    const float* ffwB    = (const float*)d_in[12];
    const float* alpha_f = (const float*)d_in[13];
    const float* final_W = (const float*)d_in[14];
    const float* final_b = (const float*)d_in[15];
    float* out = (float*)d_out;

    float *h, *dinv;
    __nv_bfloat16 *c2b, *aggb, *wb, *w0hi, *w0lo;
    int *counts, *off, *cur, *eidx, *part;
    cudaGetSymbolAddress((void**)&h, g_h);
    cudaGetSymbolAddress((void**)&c2b, g_c2b);
    cudaGetSymbolAddress((void**)&aggb, g_aggb);
    cudaGetSymbolAddress((void**)&wb, g_wb);
    cudaGetSymbolAddress((void**)&w0hi, g_w0hi);
    cudaGetSymbolAddress((void**)&w0lo, g_w0lo);
    cudaGetSymbolAddress((void**)&dinv, g_dinv);
    cudaGetSymbolAddress((void**)&counts, g_counts);
    cudaGetSymbolAddress((void**)&off, g_off);
    cudaGetSymbolAddress((void**)&cur, g_cur);
    cudaGetSymbolAddress((void**)&eidx, g_eidx);
    cudaGetSymbolAddress((void**)&part, g_part);

    const int* rowi = ei;
    const int* coli = ei + NE;

    cudaFuncSetAttribute(gemm0_kernel, cudaFuncAttributeMaxDynamicSharedMemorySize, SM_M0);
    cudaFuncSetAttribute(gemm2_kernel, cudaFuncAttributeMaxDynamicSharedMemorySize, SM_M2);
    cudaFuncSetAttribute(gemm1_kernel, cudaFuncAttributeMaxDynamicSharedMemorySize, SM_G1);

    const int GB = (NN + 63) / 64;
    const int G1 = (NN + 127) / 128;
    const int NW = DD * DD + 2 * NL * DD * DD;

    // gemm1 at capture slot #4 (control: expect ~35.1us)
    convert_w_kernel<<<(NW + 255) / 256, 256>>>(start_W, convW, ffwW, w0hi, w0lo, wb);   // 1
    gemm0_kernel<<<G1, 256, SM_M0>>>(x, w0hi, w0lo, start_b, h);                          // 2
    zero_counts_kernel<<<(NN + 255) / 256, 256>>>(counts);                                // 3
    gemm1_kernel<<<G1, 256, SM_G1>>>(h, wb, ln1_g, ln1_b, c2b);                           // 4 (capture)
    count_kernel<<<(NE + 255) / 256, 256>>>(coli, counts);                                // 5
    scan_block_kernel<<<NB_SCAN, 1024>>>(counts, off, part);
    scan_part_kernel<<<1, 32>>>(part, off);
    add_carry_kernel<<<(NN + 255) / 256, 256>>>(counts, off, part, cur, dinv);
    fill_kernel<<<(NE + 255) / 256, 256>>>(rowi, coli, cur, eidx);

    for (int i = 0; i < NL; i++) {
        if (i > 0)
            gemm1_kernel<<<G1, 256, SM_G1>>>(h, wb + (size_t)i * DD * DD,
                                             ln1_g + i * DD, ln1_b + i * DD, c2b);
        gather_kernel<<<(NN + 7) / 8, 256>>>(off, eidx, dinv, c2b, aggb);
        gemm2_kernel<<<GB, 256, SM_M2>>>(h, wb + (size_t)(NL + i) * DD * DD,
                                         ffwB + i * DD,
                                         ln2_g + i * DD, ln2_b + i * DD,
                                         aggb, convB + i * DD,
                                         alpha_g + i, alpha_f + i, h);
    }

    final_kernel<<<(NN + 31) / 32, 128>>>(h, final_W, final_b, out);
}

// round 16
// speedup vs baseline: 1.0479x; 1.0111x over previous
#include <cuda_runtime.h>
#include <cuda_bf16.h>
#include <math.h>

#define NN 100000
#define NE 1600000
#define DD 128
#define CC 40
#define NL 3
#define NB_SCAN 98

__device__ float          g_h[(size_t)NN * DD];
__device__ __nv_bfloat16  g_c2b[(size_t)NN * DD];
__device__ __nv_bfloat16  g_aggb[(size_t)NN * DD];
__device__ __nv_bfloat16  g_wb[6 * DD * DD];
__device__ __nv_bfloat16  g_w0hi[DD * DD];
__device__ __nv_bfloat16  g_w0lo[DD * DD];
__device__ float g_dinv[NN];
__device__ int g_counts[NN], g_off[NN + 1], g_cur[NN], g_eidx[NE], g_part[128];

typedef unsigned long long u64;
typedef unsigned int u32;

__device__ __forceinline__ float siluf(float x) { return x / (1.0f + expf(-x)); }

__device__ __forceinline__ float warp_sum(float v) {
#pragma unroll
    for (int o = 16; o > 0; o >>= 1) v += __shfl_xor_sync(0xffffffffu, v, o);
    return v;
}
__device__ __forceinline__ float4 ldb4(const __nv_bfloat16* p) {
    uint2 u = *(const uint2*)p;
    __nv_bfloat162 a = *reinterpret_cast<const __nv_bfloat162*>(&u.x);
    __nv_bfloat162 b = *reinterpret_cast<const __nv_bfloat162*>(&u.y);
    float2 fa = __bfloat1622float2(a), fb = __bfloat1622float2(b);
    return make_float4(fa.x, fa.y, fb.x, fb.y);
}
__device__ __forceinline__ u32 pkbf2(float a, float b) {
    __nv_bfloat162 t = __floats2bfloat162_rn(a, b);
    return *reinterpret_cast<u32*>(&t);
}
__device__ __forceinline__ void unp8(uint4 u, float* o) {
    __nv_bfloat162 p0 = *reinterpret_cast<__nv_bfloat162*>(&u.x);
    __nv_bfloat162 p1 = *reinterpret_cast<__nv_bfloat162*>(&u.y);
    __nv_bfloat162 p2 = *reinterpret_cast<__nv_bfloat162*>(&u.z);
    __nv_bfloat162 p3 = *reinterpret_cast<__nv_bfloat162*>(&u.w);
    float2 f0 = __bfloat1622float2(p0), f1 = __bfloat1622float2(p1);
    float2 f2 = __bfloat1622float2(p2), f3 = __bfloat1622float2(p3);
    o[0] = f0.x; o[1] = f0.y; o[2] = f1.x; o[3] = f1.y;
    o[4] = f2.x; o[5] = f2.y; o[6] = f3.x; o[7] = f3.y;
}
__device__ __forceinline__ void ldsm4(u32* f, u32 addr) {
    asm volatile("ldmatrix.sync.aligned.m8n8.x4.shared.b16 {%0,%1,%2,%3}, [%4];"
                 : "=r"(f[0]), "=r"(f[1]), "=r"(f[2]), "=r"(f[3]) : "r"(addr));
}
__device__ __forceinline__ void ldsm2t(u32* f, u32 addr) {
    asm volatile("ldmatrix.sync.aligned.m8n8.x2.trans.shared.b16 {%0,%1}, [%2];"
                 : "=r"(f[0]), "=r"(f[1]) : "r"(addr));
}
__device__ __forceinline__ void mma16816(float* c, const u32* a, const u32* b) {
    asm volatile("mma.sync.aligned.m16n8k16.row.col.f32.bf16.bf16.f32 "
                 "{%0,%1,%2,%3}, {%4,%5,%6,%7}, {%8,%9}, {%0,%1,%2,%3};"
                 : "+f"(c[0]), "+f"(c[1]), "+f"(c[2]), "+f"(c[3])
                 : "r"(a[0]), "r"(a[1]), "r"(a[2]), "r"(a[3]), "r"(b[0]), "r"(b[1]));
}

// ---------------- weight conversion ----------------
__global__ void convert_w_kernel(const float* __restrict__ startW,
                                 const float* __restrict__ convW,
                                 const float* __restrict__ ffwW,
                                 __nv_bfloat16* __restrict__ w0hi,
                                 __nv_bfloat16* __restrict__ w0lo,
                                 __nv_bfloat16* __restrict__ wb) {
    const int i = blockIdx.x * blockDim.x + threadIdx.x;
    const int s = DD * DD, per = NL * DD * DD;
    if (i < s) {
        float v = startW[i];
        __nv_bfloat16 hi = __float2bfloat16(v);
        w0hi[i] = hi;
        w0lo[i] = __float2bfloat16(v - __bfloat162float(hi));
    } else if (i < s + per) {
        wb[i - s] = __float2bfloat16(convW[i - s]);
    } else if (i < s + 2 * per) {
        wb[i - s] = __float2bfloat16(ffwW[i - s - per]);
    }
}

// ---------------- CSR build ----------------
__global__ void zero_counts_kernel(int* c) { int i = blockIdx.x * blockDim.x + threadIdx.x; if (i < NN) c[i] = 0; }
__global__ void count_kernel(const int* __restrict__ col, int* __restrict__ c) {
    int e = blockIdx.x * blockDim.x + threadIdx.x; if (e < NE) atomicAdd(&c[col[e]], 1);
}
__global__ void dinv_kernel(const int* __restrict__ c, float* __restrict__ d) {
    int i = blockIdx.x * blockDim.x + threadIdx.x; if (i < NN) d[i] = rsqrtf((float)(c[i] + 1));
}
__global__ void __launch_bounds__(1024) scan_block_kernel(const int* __restrict__ counts,
                                                          int* __restrict__ off, int* __restrict__ part) {
    __shared__ int wsum[32];
    const int t = threadIdx.x, lane = t & 31, w = t >> 5;
    const int i = blockIdx.x * 1024 + t;
    const int v = (i < NN) ? counts[i] : 0;
    int x = v;
#pragma unroll
    for (int o = 1; o < 32; o <<= 1) { int y = __shfl_up_sync(0xffffffffu, x, o); if (lane >= o) x += y; }
    if (lane == 31) wsum[w] = x;
    __syncthreads();
    if (w == 0) {
        int y = wsum[lane];
#pragma unroll
        for (int o = 1; o < 32; o <<= 1) { int z = __shfl_up_sync(0xffffffffu, y, o); if (lane >= o) y += z; }
        wsum[lane] = y;
    }
    __syncthreads();
    const int incl = x + (w > 0 ? wsum[w - 1] : 0);
    if (i < NN) off[i + 1] = incl;
    if (t == 1023) part[blockIdx.x] = incl;
}
__global__ void scan_part_kernel(int* __restrict__ part, int* __restrict__ off) {
    const int lane = threadIdx.x;
    int carry = 0;
    for (int base = 0; base < 128; base += 32) {
        const int idx = base + lane;
        const int v = (idx < NB_SCAN) ? part[idx] : 0;
        int x = v;
#pragma unroll
        for (int o = 1; o < 32; o <<= 1) { int y = __shfl_up_sync(0xffffffffu, x, o); if (lane >= o) x += y; }
        if (idx < NB_SCAN) part[idx] = carry + x - v;
        carry += __shfl_sync(0xffffffffu, x, 31);
    }
    if (lane == 0) off[0] = 0;
}
__global__ void add_carry_kernel(const int* __restrict__ counts, int* __restrict__ off,
                                 const int* __restrict__ part, int* __restrict__ cur) {
    const int i = blockIdx.x * blockDim.x + threadIdx.x;
    if (i >= NN) return;
    const int o = off[i + 1] + part[i >> 10];
    off[i + 1] = o; cur[i] = o - counts[i];
}
__global__ void fill_kernel(const int* __restrict__ rowi, const int* __restrict__ coli,
                            int* __restrict__ cur, int* __restrict__ eidx) {
    int e = blockIdx.x * blockDim.x + threadIdx.x;
    if (e < NE) { int p = atomicAdd(&cur[coli[e]], 1); eidx[p] = rowi[e]; }
}

#define LDAB 136
#define LDC  132

// ---------------- conv GEMM: 128x128 block; output row-scaled by dinv[r] ----------------
#define SM_G1 69632
__global__ void __launch_bounds__(256, 2) gemm1_kernel(
    const float* __restrict__ in, const __nv_bfloat16* __restrict__ Wb,
    const float* __restrict__ lng, const float* __restrict__ lnb,
    const float* __restrict__ dinv,
    __nv_bfloat16* __restrict__ outb)
{
    extern __shared__ __align__(16) char smem[];
    __nv_bfloat16* Wsh = (__nv_bfloat16*)(smem);
    __nv_bfloat16* Ash = (__nv_bfloat16*)(smem + 34816);
    const int tid = threadIdx.x, wid = tid >> 5, lane = tid & 31;
    const int row0 = blockIdx.x * 128;

    {
        const int r = tid >> 1, half = tid & 1;
        const uint4* src = (const uint4*)(Wb + (size_t)r * DD + half * 64);
        uint4* dst = (uint4*)(Wsh + r * LDAB + half * 64);
#pragma unroll
        for (int j = 0; j < 8; j++) dst[j] = src[j];
    }
    {
        const float4 g4 = *(const float4*)(lng + lane * 4);
        const float4 b4 = *(const float4*)(lnb + lane * 4);
#pragma unroll
        for (int i = 0; i < 16; i++) {
            const int lr = wid * 16 + i;
            const int r = row0 + lr;
            float4 v = (r < NN) ? *(const float4*)(in + (size_t)r * DD + lane * 4)
                                : make_float4(0.f, 0.f, 0.f, 0.f);
            float s1 = warp_sum(v.x + v.y + v.z + v.w);
            float s2 = warp_sum(v.x * v.x + v.y * v.y + v.z * v.z + v.w * v.w);
            float mu  = s1 * (1.0f / 128.0f);
            float var = fmaxf(s2 * (1.0f / 128.0f) - mu * mu, 0.0f);
            float rs  = rsqrtf(var + 1e-5f);
            uint2 p;
            p.x = pkbf2((v.x - mu) * rs * g4.x + b4.x, (v.y - mu) * rs * g4.y + b4.y);
            p.y = pkbf2((v.z - mu) * rs * g4.z + b4.z, (v.w - mu) * rs * g4.w + b4.w);
            *(uint2*)(Ash + lr * LDAB + lane * 4) = p;
        }
    }
    __syncthreads();

    const int m0 = (wid >> 1) * 32, n0 = (wid & 1) * 64;
    const u32 a_base = (u32)__cvta_generic_to_shared(Ash);
    const u32 w_base = (u32)__cvta_generic_to_shared(Wsh);
    const int a_i = lane & 7, a_sel = lane >> 3;
    const int a_row = ((a_sel & 1) ? 8 : 0) + a_i;
    const int a_kof = (a_sel & 2) ? 8 : 0;
    const int b_row = lane & 15;

    float acc[2][8][4];
#pragma unroll
    for (int mt = 0; mt < 2; mt++)
#pragma unroll
        for (int nt = 0; nt < 8; nt++)
#pragma unroll
            for (int q = 0; q < 4; q++) acc[mt][nt][q] = 0.f;

#pragma unroll
    for (int k0 = 0; k0 < DD; k0 += 16) {
        u32 af[2][4], bf[8][2];
#pragma unroll
        for (int mt = 0; mt < 2; mt++)
            ldsm4(af[mt], a_base + (u32)((m0 + mt * 16 + a_row) * (LDAB * 2) + (k0 + a_kof) * 2));
#pragma unroll
        for (int nt = 0; nt < 8; nt++)
            ldsm2t(bf[nt], w_base + (u32)((k0 + b_row) * (LDAB * 2) + (n0 + nt * 8) * 2));
#pragma unroll
        for (int mt = 0; mt < 2; mt++)
#pragma unroll
            for (int nt = 0; nt < 8; nt++)
                mma16816(acc[mt][nt], af[mt], bf[nt]);
    }

    const int g = lane >> 2, t = lane & 3;
#pragma unroll
    for (int mt = 0; mt < 2; mt++) {
        const int r0 = row0 + m0 + mt * 16 + g;
        const int r1 = r0 + 8;
        const float d0 = (r0 < NN) ? __ldg(dinv + r0) : 0.f;
        const float d1 = (r1 < NN) ? __ldg(dinv + r1) : 0.f;
#pragma unroll
        for (int nt = 0; nt < 8; nt++) {
            const int col = n0 + nt * 8 + 2 * t;
            if (r0 < NN) *(u32*)(outb + (size_t)r0 * DD + col) = pkbf2(acc[mt][nt][0] * d0, acc[mt][nt][1] * d0);
            if (r1 < NN) *(u32*)(outb + (size_t)r1 * DD + col) = pkbf2(acc[mt][nt][2] * d1, acc[mt][nt][3] * d1);
        }
    }
}

// ---------------- start GEMM: 128x128 block, split-bf16 (measured ~85us) ----------------
#define SM_M0 139264
__global__ void __launch_bounds__(256, 1) gemm0_kernel(
    const float* __restrict__ in,
    const __nv_bfloat16* __restrict__ Whi, const __nv_bfloat16* __restrict__ Wlo,
    const float* __restrict__ bias, float* __restrict__ outf)
{
    extern __shared__ __align__(16) char smem[];
    __nv_bfloat16* Wsh  = (__nv_bfloat16*)(smem);
    __nv_bfloat16* Wlos = (__nv_bfloat16*)(smem + 34816);
    __nv_bfloat16* Ash  = (__nv_bfloat16*)(smem + 69632);
    __nv_bfloat16* Alos = (__nv_bfloat16*)(smem + 104448);
    float*         Csh  = (float*)(smem);

    const int tid = threadIdx.x, wid = tid >> 5, lane = tid & 31;
    const int row0 = blockIdx.x * 128;

    {
        const int r = tid >> 1, half = tid & 1;
        const uint4* s1 = (const uint4*)(Whi + (size_t)r * DD + half * 64);
        uint4* d1 = (uint4*)(Wsh + r * LDAB + half * 64);
#pragma unroll
        for (int j = 0; j < 8; j++) d1[j] = s1[j];
        const uint4* s2 = (const uint4*)(Wlo + (size_t)r * DD + half * 64);
        uint4* d2 = (uint4*)(Wlos + r * LDAB + half * 64);
#pragma unroll
        for (int j = 0; j < 8; j++) d2[j] = s2[j];
    }
#pragma unroll
    for (int i = 0; i < 16; i++) {
        const int lr = wid * 16 + i;
        const int r = row0 + lr;
        float4 v = (r < NN) ? *(const float4*)(in + (size_t)r * DD + lane * 4)
                            : make_float4(0.f, 0.f, 0.f, 0.f);
        __nv_bfloat16 hx = __float2bfloat16(v.x), hy = __float2bfloat16(v.y);
        __nv_bfloat16 hz = __float2bfloat16(v.z), hw = __float2bfloat16(v.w);
        uint2 phi;
        phi.x = pkbf2(__bfloat162float(hx), __bfloat162float(hy));
        phi.y = pkbf2(__bfloat162float(hz), __bfloat162float(hw));
        *(uint2*)(Ash + lr * LDAB + lane * 4) = phi;
        uint2 plo;
        plo.x = pkbf2(v.x - __bfloat162float(hx), v.y - __bfloat162float(hy));
        plo.y = pkbf2(v.z - __bfloat162float(hz), v.w - __bfloat162float(hw));
        *(uint2*)(Alos + lr * LDAB + lane * 4) = plo;
    }
    __syncthreads();

    const int m0 = (wid >> 1) * 32, n0 = (wid & 1) * 64;
    const u32 a_base  = (u32)__cvta_generic_to_shared(Ash);
    const u32 al_base = (u32)__cvta_generic_to_shared(Alos);
    const u32 w_base  = (u32)__cvta_generic_to_shared(Wsh);
    const u32 wl_base = (u32)__cvta_generic_to_shared(Wlos);
    const int a_i = lane & 7, a_sel = lane >> 3;
    const int a_row = ((a_sel & 1) ? 8 : 0) + a_i;
    const int a_kof = (a_sel & 2) ? 8 : 0;
    const int b_row = lane & 15;

    float acc[2][8][4];
#pragma unroll
    for (int mt = 0; mt < 2; mt++)
#pragma unroll
        for (int nt = 0; nt < 8; nt++)
#pragma unroll
            for (int q = 0; q < 4; q++) acc[mt][nt][q] = 0.f;

#pragma unroll
    for (int k0 = 0; k0 < DD; k0 += 16) {
        u32 ah[2][4], al[2][4], bh[8][2], bl[8][2];
#pragma unroll
        for (int mt = 0; mt < 2; mt++) {
            const u32 off = (u32)((m0 + mt * 16 + a_row) * (LDAB * 2) + (k0 + a_kof) * 2);
            ldsm4(ah[mt], a_base + off);
            ldsm4(al[mt], al_base + off);
        }
#pragma unroll
        for (int nt = 0; nt < 8; nt++) {
            const u32 off = (u32)((k0 + b_row) * (LDAB * 2) + (n0 + nt * 8) * 2);
            ldsm2t(bh[nt], w_base + off);
            ldsm2t(bl[nt], wl_base + off);
        }
#pragma unroll
        for (int mt = 0; mt < 2; mt++)
#pragma unroll
            for (int nt = 0; nt < 8; nt++) {
                mma16816(acc[mt][nt], ah[mt], bh[nt]);
                mma16816(acc[mt][nt], ah[mt], bl[nt]);
                mma16816(acc[mt][nt], al[mt], bh[nt]);
            }
    }

    __syncthreads();
    {
        const int g = lane >> 2, t = lane & 3;
#pragma unroll
        for (int mt = 0; mt < 2; mt++)
#pragma unroll
            for (int nt = 0; nt < 8; nt++) {
                const int row = m0 + mt * 16 + g;
                const int col = n0 + nt * 8 + 2 * t;
                *(float2*)(Csh + row * LDC + col)       = make_float2(acc[mt][nt][0], acc[mt][nt][1]);
                *(float2*)(Csh + (row + 8) * LDC + col) = make_float2(acc[mt][nt][2], acc[mt][nt][3]);
            }
    }
    __syncthreads();

    const float4 bias4 = *(const float4*)(bias + lane * 4);
#pragma unroll
    for (int i = 0; i < 16; i++) {
        const int lr = wid * 16 + i;
        const int r = row0 + lr;
        if (r >= NN) continue;
        float4 o = *(const float4*)(Csh + lr * LDC + lane * 4);
        o.x = siluf(o.x + bias4.x);
        o.y = siluf(o.y + bias4.y);
        o.z = siluf(o.z + bias4.z);
        o.w = siluf(o.w + bias4.w);
        *(float4*)(outf + (size_t)r * DD + lane * 4) = o;
    }
}

// ---------------- ffn GEMM (MODE 2) — R8-proven 64-row ----------------
#define SM_M2 86016
__global__ void __launch_bounds__(256, 2) gemm2_kernel(
    const float* __restrict__ in,
    const __nv_bfloat16* __restrict__ Wb,
    const float* __restrict__ bias,
    const float* __restrict__ lng,
    const float* __restrict__ lnb,
    const __nv_bfloat16* __restrict__ aggb,
    const float* __restrict__ convB,
    const float* __restrict__ alpha_g,
    const float* __restrict__ alpha_f,
    float* __restrict__ outf)
{
    extern __shared__ __align__(16) char smem[];
    __nv_bfloat16* Wsh  = (__nv_bfloat16*)(smem);
    __nv_bfloat16* Ash  = (__nv_bfloat16*)(smem + 34816);
    float*         H1sh = (float*)(smem + 52224);
    float*         Csh  = (float*)(smem);

    const int tid = threadIdx.x, wid = tid >> 5, lane = tid & 31;
    const int row0 = blockIdx.x * 64;
    const float ag = __ldg(alpha_g);

    {
        const int r = tid >> 1, half = tid & 1;
        const uint4* src = (const uint4*)(Wb + (size_t)r * DD + half * 64);
        uint4* dst = (uint4*)(Wsh + r * LDAB + half * 64);
#pragma unroll
        for (int j = 0; j < 8; j++) dst[j] = src[j];
    }
    {
        const float4 g4  = *(const float4*)(lng + lane * 4);
        const float4 b4  = *(const float4*)(lnb + lane * 4);
        const float4 cb4 = *(const float4*)(convB + lane * 4);
#pragma unroll
        for (int i = 0; i < 8; i++) {
            const int lr = wid * 8 + i;
            const int r = row0 + lr;
            float4 v = make_float4(0.f, 0.f, 0.f, 0.f);
            float4 av = make_float4(0.f, 0.f, 0.f, 0.f);
            if (r < NN) {
                v  = *(const float4*)(in + (size_t)r * DD + lane * 4);
                av = ldb4(aggb + (size_t)r * DD + lane * 4);
            }
            v.x = fmaf(ag, siluf(av.x + cb4.x), v.x);
            v.y = fmaf(ag, siluf(av.y + cb4.y), v.y);
            v.z = fmaf(ag, siluf(av.z + cb4.z), v.z);
            v.w = fmaf(ag, siluf(av.w + cb4.w), v.w);
            *(float4*)(H1sh + lr * LDC + lane * 4) = v;
            float s1 = warp_sum(v.x + v.y + v.z + v.w);
            float s2 = warp_sum(v.x * v.x + v.y * v.y + v.z * v.z + v.w * v.w);
            float mu  = s1 * (1.0f / 128.0f);
            float var = fmaxf(s2 * (1.0f / 128.0f) - mu * mu, 0.0f);
            float rs  = rsqrtf(var + 1e-5f);
            uint2 p;
            p.x = pkbf2((v.x - mu) * rs * g4.x + b4.x, (v.y - mu) * rs * g4.y + b4.y);
            p.y = pkbf2((v.z - mu) * rs * g4.z + b4.z, (v.w - mu) * rs * g4.w + b4.w);
            *(uint2*)(Ash + lr * LDAB + lane * 4) = p;
        }
    }
    __syncthreads();

    const int m0 = (wid >> 2) * 32, n0 = (wid & 3) * 32;
    const u32 a_base = (u32)__cvta_generic_to_shared(Ash);
    const u32 w_base = (u32)__cvta_generic_to_shared(Wsh);
    const int a_i = lane & 7, a_sel = lane >> 3;
    const int a_row = ((a_sel & 1) ? 8 : 0) + a_i;
    const int a_kof = (a_sel & 2) ? 8 : 0;
    const int b_row = lane & 15;

    float acc[2][4][4];
#pragma unroll
    for (int mt = 0; mt < 2; mt++)
#pragma unroll
        for (int nt = 0; nt < 4; nt++)
#pragma unroll
            for (int q = 0; q < 4; q++) acc[mt][nt][q] = 0.f;

    u32 af[2][2][4], bf[2][4][2];
#pragma unroll
    for (int mt = 0; mt < 2; mt++)
        ldsm4(af[0][mt], a_base + (u32)((m0 + mt * 16 + a_row) * (LDAB * 2) + a_kof * 2));
#pragma unroll
    for (int nt = 0; nt < 4; nt++)
        ldsm2t(bf[0][nt], w_base + (u32)(b_row * (LDAB * 2) + (n0 + nt * 8) * 2));
#pragma unroll
    for (int ks = 0; ks < 8; ks++) {
        const int cur = ks & 1;
        if (ks < 7) {
            const int k1 = (ks + 1) * 16;
#pragma unroll
            for (int mt = 0; mt < 2; mt++)
                ldsm4(af[cur ^ 1][mt], a_base + (u32)((m0 + mt * 16 + a_row) * (LDAB * 2) + (k1 + a_kof) * 2));
#pragma unroll
            for (int nt = 0; nt < 4; nt++)
                ldsm2t(bf[cur ^ 1][nt], w_base + (u32)((k1 + b_row) * (LDAB * 2) + (n0 + nt * 8) * 2));
        }
#pragma unroll
        for (int mt = 0; mt < 2; mt++)
#pragma unroll
            for (int nt = 0; nt < 4; nt++)
                mma16816(acc[mt][nt], af[cur][mt], bf[cur][nt]);
    }

    __syncthreads();
    {
        const int g = lane >> 2, t = lane & 3;
#pragma unroll
        for (int mt = 0; mt < 2; mt++)
#pragma unroll
            for (int nt = 0; nt < 4; nt++) {
                const int row = m0 + mt * 16 + g;
                const int col = n0 + nt * 8 + 2 * t;
                *(float2*)(Csh + row * LDC + col)       = make_float2(acc[mt][nt][0], acc[mt][nt][1]);
                *(float2*)(Csh + (row + 8) * LDC + col) = make_float2(acc[mt][nt][2], acc[mt][nt][3]);
            }
    }
    __syncthreads();

    const float4 bias4 = *(const float4*)(bias + lane * 4);
    const float af2 = __ldg(alpha_f);
#pragma unroll
    for (int i = 0; i < 8; i++) {
        const int lr = wid * 8 + i;
        const int r = row0 + lr;
        if (r >= NN) continue;
        float4 o = *(const float4*)(Csh + lr * LDC + lane * 4);
        const float4 h1 = *(const float4*)(H1sh + lr * LDC + lane * 4);
        o.x = fmaf(af2, siluf(o.x + bias4.x), h1.x);
        o.y = fmaf(af2, siluf(o.y + bias4.y), h1.y);
        o.z = fmaf(af2, siluf(o.z + bias4.z), h1.z);
        o.w = fmaf(af2, siluf(o.w + bias4.w), h1.w);
        *(float4*)(outf + (size_t)r * DD + lane * 4) = o;
    }
}

// ---------------- CSR gather v3: pure row sum (weights pre-folded into c2b) ----------------
// aggb[n] = dn * ( c2b[n] + sum_{r->n} c2b[r] )   (c2b rows already scaled by dinv[row])
__global__ void __launch_bounds__(256) gather_kernel(
    const int* __restrict__ off, const int* __restrict__ eidx,
    const float* __restrict__ dinv, const __nv_bfloat16* __restrict__ c2b,
    __nv_bfloat16* __restrict__ aggb)
{
    const int n = blockIdx.x * 8 + (threadIdx.x >> 5);
    if (n >= NN) return;
    const int lane = threadIdx.x & 31;
    const int half = lane >> 4;
    const int hl   = lane & 15;
    const int s = __ldg(off + n), e = __ldg(off + n + 1);
    const float dn = __ldg(dinv + n);

    float acc[8];
    {
        uint4 u = *(const uint4*)(c2b + (size_t)n * DD + hl * 8);
        float f[8]; unp8(u, f);
        const float w0 = (half == 0) ? 1.f : 0.f;
#pragma unroll
        for (int i = 0; i < 8; i++) acc[i] = w0 * f[i];
    }

    for (int j0 = s; j0 < e; j0 += 32) {
        const int jn = min(32, e - j0);
        int eid = 0;
        if (lane < jn) eid = __ldg(eidx + j0 + lane);
        for (int t = 0; t < jn; t += 8) {
            int rr[4]; float ww[4]; uint4 vv[4];
#pragma unroll
            for (int q = 0; q < 4; q++) {
                const int idx = t + 2 * q + half;
                const int src = idx & 31;
                int r = __shfl_sync(0xffffffffu, eid, src);
                const bool act = idx < jn;
                rr[q] = act ? r : 0;
                ww[q] = act ? 1.f : 0.f;
            }
#pragma unroll
            for (int q = 0; q < 4; q++)
                vv[q] = __ldg((const uint4*)(c2b + (size_t)rr[q] * DD + hl * 8));
#pragma unroll
            for (int q = 0; q < 4; q++) {
                float f[8]; unp8(vv[q], f);
#pragma unroll
                for (int i = 0; i < 8; i++) acc[i] = fmaf(ww[q], f[i], acc[i]);
            }
        }
    }

#pragma unroll
    for (int i = 0; i < 8; i++) {
        acc[i] += __shfl_xor_sync(0xffffffffu, acc[i], 16);
        acc[i] *= dn;
    }
    if (half == 0) {
        uint4 o;
        o.x = pkbf2(acc[0], acc[1]);
        o.y = pkbf2(acc[2], acc[3]);
        o.z = pkbf2(acc[4], acc[5]);
        o.w = pkbf2(acc[6], acc[7]);
        *(uint4*)(aggb + (size_t)n * DD + hl * 8) = o;
    }
}

// ---------------- final: logits + log_softmax ----------------
__global__ void __launch_bounds__(128) final_kernel(
    const float* __restrict__ h, const float* __restrict__ Wf,
    const float* __restrict__ fb, float* __restrict__ out)
{
    __shared__ float Wsh[DD * CC];
    __shared__ float bsh[CC];
    __shared__ float rowbuf[4][DD];
    const int tid = threadIdx.x;
    for (int i = tid; i < DD * CC; i += 128) Wsh[i] = Wf[i];
    if (tid < CC) bsh[tid] = fb[tid];
    __syncthreads();

    const int wid = tid >> 5, lane = tid & 31;
    const int rbase = blockIdx.x * 32 + wid * 8;
    const bool has1 = (lane < CC - 32);

    for (int ri = 0; ri < 8; ri++) {
        const int r = rbase + ri;
        if (r >= NN) return;
        float4 v = *(const float4*)(h + (size_t)r * DD + lane * 4);
        *(float4*)(&rowbuf[wid][lane * 4]) = v;
        __syncwarp();
        float acc0 = bsh[lane];
        float acc1 = has1 ? bsh[32 + lane] : 0.f;
#pragma unroll 4
        for (int k = 0; k < DD; k++) {
            float hv = rowbuf[wid][k];
            acc0 = fmaf(hv, Wsh[k * CC + lane], acc0);
            if (has1) acc1 = fmaf(hv, Wsh[k * CC + 32 + lane], acc1);
        }
        float m = has1 ? fmaxf(acc0, acc1) : acc0;
#pragma unroll
        for (int o = 16; o > 0; o >>= 1) m = fmaxf(m, __shfl_xor_sync(0xffffffffu, m, o));
        float s = expf(acc0 - m) + (has1 ? expf(acc1 - m) : 0.f);
#pragma unroll
        for (int o = 16; o > 0; o >>= 1) s += __shfl_xor_sync(0xffffffffu, s, o);
        const float ls = logf(s);
        out[(size_t)r * CC + lane] = acc0 - m - ls;
        if (has1) out[(size_t)r * CC + 32 + lane] = acc1 - m - ls;
        __syncwarp();
    }
}

// ---------------- launch ----------------
extern "C" void kernel_launch(void* const* d_in, const int* in_sizes, int n_in,
                              void* d_out, int out_size)
{
    const float* x       = (const float*)d_in[0];
    const int*   ei      = (const int*)  d_in[1];
    const float* start_W = (const float*)d_in[2];
    const float* start_b = (const float*)d_in[3];
    const float* ln1_g   = (const float*)d_in[4];
    const float* ln1_b   = (const float*)d_in[5];
    const float* convW   = (const float*)d_in[6];
    const float* convB   = (const float*)d_in[7];
    const float* alpha_g = (const float*)d_in[8];
    const float* ln2_g   = (const float*)d_in[9];
    const float* ln2_b   = (const float*)d_in[10];
    const float* ffwW    = (const float*)d_in[11];
    const float* ffwB    = (const float*)d_in[12];
    const float* alpha_f = (const float*)d_in[13];
    const float* final_W = (const float*)d_in[14];
    const float* final_b = (const float*)d_in[15];
    float* out = (float*)d_out;

    float *h, *dinv;
    __nv_bfloat16 *c2b, *aggb, *wb, *w0hi, *w0lo;
    int *counts, *off, *cur, *eidx, *part;
    cudaGetSymbolAddress((void**)&h, g_h);
    cudaGetSymbolAddress((void**)&c2b, g_c2b);
    cudaGetSymbolAddress((void**)&aggb, g_aggb);
    cudaGetSymbolAddress((void**)&wb, g_wb);
    cudaGetSymbolAddress((void**)&w0hi, g_w0hi);
    cudaGetSymbolAddress((void**)&w0lo, g_w0lo);
    cudaGetSymbolAddress((void**)&dinv, g_dinv);
    cudaGetSymbolAddress((void**)&counts, g_counts);
    cudaGetSymbolAddress((void**)&off, g_off);
    cudaGetSymbolAddress((void**)&cur, g_cur);
    cudaGetSymbolAddress((void**)&eidx, g_eidx);
    cudaGetSymbolAddress((void**)&part, g_part);

    const int* rowi = ei;
    const int* coli = ei + NE;

    cudaFuncSetAttribute(gemm0_kernel, cudaFuncAttributeMaxDynamicSharedMemorySize, SM_M0);
    cudaFuncSetAttribute(gemm2_kernel, cudaFuncAttributeMaxDynamicSharedMemorySize, SM_M2);
    cudaFuncSetAttribute(gemm1_kernel, cudaFuncAttributeMaxDynamicSharedMemorySize, SM_G1);

    const int GB = (NN + 63) / 64;
    const int G1 = (NN + 127) / 128;
    const int NW = DD * DD + 2 * NL * DD * DD;

    // capture slot #4 = count_kernel (first look at the edge-atomic histogram)
    convert_w_kernel<<<(NW + 255) / 256, 256>>>(start_W, convW, ffwW, w0hi, w0lo, wb);   // 1
    gemm0_kernel<<<G1, 256, SM_M0>>>(x, w0hi, w0lo, start_b, h);                          // 2
    zero_counts_kernel<<<(NN + 255) / 256, 256>>>(counts);                                // 3
    count_kernel<<<(NE + 255) / 256, 256>>>(coli, counts);                                // 4 (capture)
    dinv_kernel<<<(NN + 255) / 256, 256>>>(counts, dinv);                                 // 5
    gemm1_kernel<<<G1, 256, SM_G1>>>(h, wb, ln1_g, ln1_b, dinv, c2b);                     // 6 (layer 0 conv)
    scan_block_kernel<<<NB_SCAN, 1024>>>(counts, off, part);                              // 7
    scan_part_kernel<<<1, 32>>>(part, off);                                               // 8
    add_carry_kernel<<<(NN + 255) / 256, 256>>>(counts, off, part, cur);                  // 9
    fill_kernel<<<(NE + 255) / 256, 256>>>(rowi, coli, cur, eidx);                        // 10

    for (int i = 0; i < NL; i++) {
        if (i > 0)
            gemm1_kernel<<<G1, 256, SM_G1>>>(h, wb + (size_t)i * DD * DD,
                                             ln1_g + i * DD, ln1_b + i * DD, dinv, c2b);
        gather_kernel<<<(NN + 7) / 8, 256>>>(off, eidx, dinv, c2b, aggb);
        gemm2_kernel<<<GB, 256, SM_M2>>>(h, wb + (size_t)(NL + i) * DD * DD,
                                         ffwB + i * DD,
                                         ln2_g + i * DD, ln2_b + i * DD,
                                         aggb, convB + i * DD,
                                         alpha_g + i, alpha_f + i, h);
    }

    final_kernel<<<(NN + 31) / 32, 128>>>(h, final_W, final_b, out);
}

// round 17
// speedup vs baseline: 1.0756x; 1.0264x over previous
#include <cuda_runtime.h>
#include <cuda_bf16.h>
#include <math.h>

#define NN 100000
#define NE 1600000
#define DD 128
#define CC 40
#define NL 3
#define NB_SCAN 98

__device__ float          g_h[(size_t)NN * DD];
__device__ float          g_h1[(size_t)NN * DD];   // fp32 h1 (residual basis), produced by gather
__device__ __nv_bfloat16  g_c2b[(size_t)NN * DD];
__device__ __nv_bfloat16  g_wb[6 * DD * DD];
__device__ __nv_bfloat16  g_w0hi[DD * DD];
__device__ __nv_bfloat16  g_w0lo[DD * DD];
__device__ float g_dinv[NN];
__device__ int g_counts[NN], g_off[NN + 1], g_cur[NN], g_eidx[NE], g_part[128];

typedef unsigned long long u64;
typedef unsigned int u32;

__device__ __forceinline__ float siluf(float x) { return x / (1.0f + expf(-x)); }

__device__ __forceinline__ float warp_sum(float v) {
#pragma unroll
    for (int o = 16; o > 0; o >>= 1) v += __shfl_xor_sync(0xffffffffu, v, o);
    return v;
}
__device__ __forceinline__ u32 pkbf2(float a, float b) {
    __nv_bfloat162 t = __floats2bfloat162_rn(a, b);
    return *reinterpret_cast<u32*>(&t);
}
__device__ __forceinline__ void unp8(uint4 u, float* o) {
    __nv_bfloat162 p0 = *reinterpret_cast<__nv_bfloat162*>(&u.x);
    __nv_bfloat162 p1 = *reinterpret_cast<__nv_bfloat162*>(&u.y);
    __nv_bfloat162 p2 = *reinterpret_cast<__nv_bfloat162*>(&u.z);
    __nv_bfloat162 p3 = *reinterpret_cast<__nv_bfloat162*>(&u.w);
    float2 f0 = __bfloat1622float2(p0), f1 = __bfloat1622float2(p1);
    float2 f2 = __bfloat1622float2(p2), f3 = __bfloat1622float2(p3);
    o[0] = f0.x; o[1] = f0.y; o[2] = f1.x; o[3] = f1.y;
    o[4] = f2.x; o[5] = f2.y; o[6] = f3.x; o[7] = f3.y;
}
__device__ __forceinline__ void ldsm4(u32* f, u32 addr) {
    asm volatile("ldmatrix.sync.aligned.m8n8.x4.shared.b16 {%0,%1,%2,%3}, [%4];"
                 : "=r"(f[0]), "=r"(f[1]), "=r"(f[2]), "=r"(f[3]) : "r"(addr));
}
__device__ __forceinline__ void ldsm2t(u32* f, u32 addr) {
    asm volatile("ldmatrix.sync.aligned.m8n8.x2.trans.shared.b16 {%0,%1}, [%2];"
                 : "=r"(f[0]), "=r"(f[1]) : "r"(addr));
}
__device__ __forceinline__ void mma16816(float* c, const u32* a, const u32* b) {
    asm volatile("mma.sync.aligned.m16n8k16.row.col.f32.bf16.bf16.f32 "
                 "{%0,%1,%2,%3}, {%4,%5,%6,%7}, {%8,%9}, {%0,%1,%2,%3};"
                 : "+f"(c[0]), "+f"(c[1]), "+f"(c[2]), "+f"(c[3])
                 : "r"(a[0]), "r"(a[1]), "r"(a[2]), "r"(a[3]), "r"(b[0]), "r"(b[1]));
}

// ---------------- weight conversion ----------------
__global__ void convert_w_kernel(const float* __restrict__ startW,
                                 const float* __restrict__ convW,
                                 const float* __restrict__ ffwW,
                                 __nv_bfloat16* __restrict__ w0hi,
                                 __nv_bfloat16* __restrict__ w0lo,
                                 __nv_bfloat16* __restrict__ wb) {
    const int i = blockIdx.x * blockDim.x + threadIdx.x;
    const int s = DD * DD, per = NL * DD * DD;
    if (i < s) {
        float v = startW[i];
        __nv_bfloat16 hi = __float2bfloat16(v);
        w0hi[i] = hi;
        w0lo[i] = __float2bfloat16(v - __bfloat162float(hi));
    } else if (i < s + per) {
        wb[i - s] = __float2bfloat16(convW[i - s]);
    } else if (i < s + 2 * per) {
        wb[i - s] = __float2bfloat16(ffwW[i - s - per]);
    }
}

// ---------------- CSR build ----------------
__global__ void zero_counts_kernel(int* c) { int i = blockIdx.x * blockDim.x + threadIdx.x; if (i < NN) c[i] = 0; }
__global__ void count_kernel(const int* __restrict__ col, int* __restrict__ c) {
    int e = blockIdx.x * blockDim.x + threadIdx.x; if (e < NE) atomicAdd(&c[col[e]], 1);
}
__global__ void dinv_kernel(const int* __restrict__ c, float* __restrict__ d) {
    int i = blockIdx.x * blockDim.x + threadIdx.x; if (i < NN) d[i] = rsqrtf((float)(c[i] + 1));
}
__global__ void __launch_bounds__(1024) scan_block_kernel(const int* __restrict__ counts,
                                                          int* __restrict__ off, int* __restrict__ part) {
    __shared__ int wsum[32];
    const int t = threadIdx.x, lane = t & 31, w = t >> 5;
    const int i = blockIdx.x * 1024 + t;
    const int v = (i < NN) ? counts[i] : 0;
    int x = v;
#pragma unroll
    for (int o = 1; o < 32; o <<= 1) { int y = __shfl_up_sync(0xffffffffu, x, o); if (lane >= o) x += y; }
    if (lane == 31) wsum[w] = x;
    __syncthreads();
    if (w == 0) {
        int y = wsum[lane];
#pragma unroll
        for (int o = 1; o < 32; o <<= 1) { int z = __shfl_up_sync(0xffffffffu, y, o); if (lane >= o) y += z; }
        wsum[lane] = y;
    }
    __syncthreads();
    const int incl = x + (w > 0 ? wsum[w - 1] : 0);
    if (i < NN) off[i + 1] = incl;
    if (t == 1023) part[blockIdx.x] = incl;
}
__global__ void scan_part_kernel(int* __restrict__ part, int* __restrict__ off) {
    const int lane = threadIdx.x;
    int carry = 0;
    for (int base = 0; base < 128; base += 32) {
        const int idx = base + lane;
        const int v = (idx < NB_SCAN) ? part[idx] : 0;
        int x = v;
#pragma unroll
        for (int o = 1; o < 32; o <<= 1) { int y = __shfl_up_sync(0xffffffffu, x, o); if (lane >= o) x += y; }
        if (idx < NB_SCAN) part[idx] = carry + x - v;
        carry += __shfl_sync(0xffffffffu, x, 31);
    }
    if (lane == 0) off[0] = 0;
}
__global__ void add_carry_kernel(const int* __restrict__ counts, int* __restrict__ off,
                                 const int* __restrict__ part, int* __restrict__ cur) {
    const int i = blockIdx.x * blockDim.x + threadIdx.x;
    if (i >= NN) return;
    const int o = off[i + 1] + part[i >> 10];
    off[i + 1] = o; cur[i] = o - counts[i];
}
__global__ void fill_kernel(const int* __restrict__ rowi, const int* __restrict__ coli,
                            int* __restrict__ cur, int* __restrict__ eidx) {
    int e = blockIdx.x * blockDim.x + threadIdx.x;
    if (e < NE) { int p = atomicAdd(&cur[coli[e]], 1); eidx[p] = rowi[e]; }
}

#define LDAB 136
#define LDC  132

// ---------------- conv GEMM: 128x128 block; output row-scaled by dinv[r] (measured shape) ----------------
#define SM_G1 69632
__global__ void __launch_bounds__(256, 2) gemm1_kernel(
    const float* __restrict__ in, const __nv_bfloat16* __restrict__ Wb,
    const float* __restrict__ lng, const float* __restrict__ lnb,
    const float* __restrict__ dinv,
    __nv_bfloat16* __restrict__ outb)
{
    extern __shared__ __align__(16) char smem[];
    __nv_bfloat16* Wsh = (__nv_bfloat16*)(smem);
    __nv_bfloat16* Ash = (__nv_bfloat16*)(smem + 34816);
    const int tid = threadIdx.x, wid = tid >> 5, lane = tid & 31;
    const int row0 = blockIdx.x * 128;

    {
        const int r = tid >> 1, half = tid & 1;
        const uint4* src = (const uint4*)(Wb + (size_t)r * DD + half * 64);
        uint4* dst = (uint4*)(Wsh + r * LDAB + half * 64);
#pragma unroll
        for (int j = 0; j < 8; j++) dst[j] = src[j];
    }
    {
        const float4 g4 = *(const float4*)(lng + lane * 4);
        const float4 b4 = *(const float4*)(lnb + lane * 4);
#pragma unroll
        for (int i = 0; i < 16; i++) {
            const int lr = wid * 16 + i;
            const int r = row0 + lr;
            float4 v = (r < NN) ? *(const float4*)(in + (size_t)r * DD + lane * 4)
                                : make_float4(0.f, 0.f, 0.f, 0.f);
            float s1 = warp_sum(v.x + v.y + v.z + v.w);
            float s2 = warp_sum(v.x * v.x + v.y * v.y + v.z * v.z + v.w * v.w);
            float mu  = s1 * (1.0f / 128.0f);
            float var = fmaxf(s2 * (1.0f / 128.0f) - mu * mu, 0.0f);
            float rs  = rsqrtf(var + 1e-5f);
            uint2 p;
            p.x = pkbf2((v.x - mu) * rs * g4.x + b4.x, (v.y - mu) * rs * g4.y + b4.y);
            p.y = pkbf2((v.z - mu) * rs * g4.z + b4.z, (v.w - mu) * rs * g4.w + b4.w);
            *(uint2*)(Ash + lr * LDAB + lane * 4) = p;
        }
    }
    __syncthreads();

    const int m0 = (wid >> 1) * 32, n0 = (wid & 1) * 64;
    const u32 a_base = (u32)__cvta_generic_to_shared(Ash);
    const u32 w_base = (u32)__cvta_generic_to_shared(Wsh);
    const int a_i = lane & 7, a_sel = lane >> 3;
    const int a_row = ((a_sel & 1) ? 8 : 0) + a_i;
    const int a_kof = (a_sel & 2) ? 8 : 0;
    const int b_row = lane & 15;

    float acc[2][8][4];
#pragma unroll
    for (int mt = 0; mt < 2; mt++)
#pragma unroll
        for (int nt = 0; nt < 8; nt++)
#pragma unroll
            for (int q = 0; q < 4; q++) acc[mt][nt][q] = 0.f;

#pragma unroll
    for (int k0 = 0; k0 < DD; k0 += 16) {
        u32 af[2][4], bf[8][2];
#pragma unroll
        for (int mt = 0; mt < 2; mt++)
            ldsm4(af[mt], a_base + (u32)((m0 + mt * 16 + a_row) * (LDAB * 2) + (k0 + a_kof) * 2));
#pragma unroll
        for (int nt = 0; nt < 8; nt++)
            ldsm2t(bf[nt], w_base + (u32)((k0 + b_row) * (LDAB * 2) + (n0 + nt * 8) * 2));
#pragma unroll
        for (int mt = 0; mt < 2; mt++)
#pragma unroll
            for (int nt = 0; nt < 8; nt++)
                mma16816(acc[mt][nt], af[mt], bf[nt]);
    }

    const int g = lane >> 2, t = lane & 3;
#pragma unroll
    for (int mt = 0; mt < 2; mt++) {
        const int r0 = row0 + m0 + mt * 16 + g;
        const int r1 = r0 + 8;
        const float d0 = (r0 < NN) ? __ldg(dinv + r0) : 0.f;
        const float d1 = (r1 < NN) ? __ldg(dinv + r1) : 0.f;
#pragma unroll
        for (int nt = 0; nt < 8; nt++) {
            const int col = n0 + nt * 8 + 2 * t;
            if (r0 < NN) *(u32*)(outb + (size_t)r0 * DD + col) = pkbf2(acc[mt][nt][0] * d0, acc[mt][nt][1] * d0);
            if (r1 < NN) *(u32*)(outb + (size_t)r1 * DD + col) = pkbf2(acc[mt][nt][2] * d1, acc[mt][nt][3] * d1);
        }
    }
}

// ---------------- ffn GEMM v3: gemm1-clone (128-row), h1buf in/out ----------------
// out = af * silu( LN(h1) @ W + bias ) + h1     (direct fragment epilogue, no C staging)
#define SM_G2 69632
__global__ void __launch_bounds__(256, 2) gemm2_kernel(
    const float* __restrict__ h1buf, const __nv_bfloat16* __restrict__ Wb,
    const float* __restrict__ bias,
    const float* __restrict__ lng, const float* __restrict__ lnb,
    const float* __restrict__ alpha_f,
    float* __restrict__ outf)
{
    extern __shared__ __align__(16) char smem[];
    __nv_bfloat16* Wsh = (__nv_bfloat16*)(smem);
    __nv_bfloat16* Ash = (__nv_bfloat16*)(smem + 34816);
    const int tid = threadIdx.x, wid = tid >> 5, lane = tid & 31;
    const int row0 = blockIdx.x * 128;

    {
        const int r = tid >> 1, half = tid & 1;
        const uint4* src = (const uint4*)(Wb + (size_t)r * DD + half * 64);
        uint4* dst = (uint4*)(Wsh + r * LDAB + half * 64);
#pragma unroll
        for (int j = 0; j < 8; j++) dst[j] = src[j];
    }
    {
        const float4 g4 = *(const float4*)(lng + lane * 4);
        const float4 b4 = *(const float4*)(lnb + lane * 4);
#pragma unroll
        for (int i = 0; i < 16; i++) {
            const int lr = wid * 16 + i;
            const int r = row0 + lr;
            float4 v = (r < NN) ? *(const float4*)(h1buf + (size_t)r * DD + lane * 4)
                                : make_float4(0.f, 0.f, 0.f, 0.f);
            float s1 = warp_sum(v.x + v.y + v.z + v.w);
            float s2 = warp_sum(v.x * v.x + v.y * v.y + v.z * v.z + v.w * v.w);
            float mu  = s1 * (1.0f / 128.0f);
            float var = fmaxf(s2 * (1.0f / 128.0f) - mu * mu, 0.0f);
            float rs  = rsqrtf(var + 1e-5f);
            uint2 p;
            p.x = pkbf2((v.x - mu) * rs * g4.x + b4.x, (v.y - mu) * rs * g4.y + b4.y);
            p.y = pkbf2((v.z - mu) * rs * g4.z + b4.z, (v.w - mu) * rs * g4.w + b4.w);
            *(uint2*)(Ash + lr * LDAB + lane * 4) = p;
        }
    }
    __syncthreads();

    const int m0 = (wid >> 1) * 32, n0 = (wid & 1) * 64;
    const u32 a_base = (u32)__cvta_generic_to_shared(Ash);
    const u32 w_base = (u32)__cvta_generic_to_shared(Wsh);
    const int a_i = lane & 7, a_sel = lane >> 3;
    const int a_row = ((a_sel & 1) ? 8 : 0) + a_i;
    const int a_kof = (a_sel & 2) ? 8 : 0;
    const int b_row = lane & 15;

    float acc[2][8][4];
#pragma unroll
    for (int mt = 0; mt < 2; mt++)
#pragma unroll
        for (int nt = 0; nt < 8; nt++)
#pragma unroll
            for (int q = 0; q < 4; q++) acc[mt][nt][q] = 0.f;

#pragma unroll
    for (int k0 = 0; k0 < DD; k0 += 16) {
        u32 af[2][4], bf[8][2];
#pragma unroll
        for (int mt = 0; mt < 2; mt++)
            ldsm4(af[mt], a_base + (u32)((m0 + mt * 16 + a_row) * (LDAB * 2) + (k0 + a_kof) * 2));
#pragma unroll
        for (int nt = 0; nt < 8; nt++)
            ldsm2t(bf[nt], w_base + (u32)((k0 + b_row) * (LDAB * 2) + (n0 + nt * 8) * 2));
#pragma unroll
        for (int mt = 0; mt < 2; mt++)
#pragma unroll
            for (int nt = 0; nt < 8; nt++)
                mma16816(acc[mt][nt], af[mt], bf[nt]);
    }

    // direct fragment epilogue: out = af*silu(acc + bias) + h1
    const float af2 = __ldg(alpha_f);
    const int g = lane >> 2, t = lane & 3;
#pragma unroll
    for (int mt = 0; mt < 2; mt++) {
        const int r0 = row0 + m0 + mt * 16 + g;
        const int r1 = r0 + 8;
#pragma unroll
        for (int nt = 0; nt < 8; nt++) {
            const int col = n0 + nt * 8 + 2 * t;
            const float b0 = __ldg(bias + col), b1 = __ldg(bias + col + 1);
            if (r0 < NN) {
                const float2 h1 = *(const float2*)(h1buf + (size_t)r0 * DD + col);
                float2 o;
                o.x = fmaf(af2, siluf(acc[mt][nt][0] + b0), h1.x);
                o.y = fmaf(af2, siluf(acc[mt][nt][1] + b1), h1.y);
                *(float2*)(outf + (size_t)r0 * DD + col) = o;
            }
            if (r1 < NN) {
                const float2 h1 = *(const float2*)(h1buf + (size_t)r1 * DD + col);
                float2 o;
                o.x = fmaf(af2, siluf(acc[mt][nt][2] + b0), h1.x);
                o.y = fmaf(af2, siluf(acc[mt][nt][3] + b1), h1.y);
                *(float2*)(outf + (size_t)r1 * DD + col) = o;
            }
        }
    }
}

// ---------------- start GEMM: 128x128 block, split-bf16 ----------------
#define SM_M0 139264
__global__ void __launch_bounds__(256, 1) gemm0_kernel(
    const float* __restrict__ in,
    const __nv_bfloat16* __restrict__ Whi, const __nv_bfloat16* __restrict__ Wlo,
    const float* __restrict__ bias, float* __restrict__ outf)
{
    extern __shared__ __align__(16) char smem[];
    __nv_bfloat16* Wsh  = (__nv_bfloat16*)(smem);
    __nv_bfloat16* Wlos = (__nv_bfloat16*)(smem + 34816);
    __nv_bfloat16* Ash  = (__nv_bfloat16*)(smem + 69632);
    __nv_bfloat16* Alos = (__nv_bfloat16*)(smem + 104448);
    float*         Csh  = (float*)(smem);

    const int tid = threadIdx.x, wid = tid >> 5, lane = tid & 31;
    const int row0 = blockIdx.x * 128;

    {
        const int r = tid >> 1, half = tid & 1;
        const uint4* s1 = (const uint4*)(Whi + (size_t)r * DD + half * 64);
        uint4* d1 = (uint4*)(Wsh + r * LDAB + half * 64);
#pragma unroll
        for (int j = 0; j < 8; j++) d1[j] = s1[j];
        const uint4* s2 = (const uint4*)(Wlo + (size_t)r * DD + half * 64);
        uint4* d2 = (uint4*)(Wlos + r * LDAB + half * 64);
#pragma unroll
        for (int j = 0; j < 8; j++) d2[j] = s2[j];
    }
#pragma unroll
    for (int i = 0; i < 16; i++) {
        const int lr = wid * 16 + i;
        const int r = row0 + lr;
        float4 v = (r < NN) ? *(const float4*)(in + (size_t)r * DD + lane * 4)
                            : make_float4(0.f, 0.f, 0.f, 0.f);
        __nv_bfloat16 hx = __float2bfloat16(v.x), hy = __float2bfloat16(v.y);
        __nv_bfloat16 hz = __float2bfloat16(v.z), hw = __float2bfloat16(v.w);
        uint2 phi;
        phi.x = pkbf2(__bfloat162float(hx), __bfloat162float(hy));
        phi.y = pkbf2(__bfloat162float(hz), __bfloat162float(hw));
        *(uint2*)(Ash + lr * LDAB + lane * 4) = phi;
        uint2 plo;
        plo.x = pkbf2(v.x - __bfloat162float(hx), v.y - __bfloat162float(hy));
        plo.y = pkbf2(v.z - __bfloat162float(hz), v.w - __bfloat162float(hw));
        *(uint2*)(Alos + lr * LDAB + lane * 4) = plo;
    }
    __syncthreads();

    const int m0 = (wid >> 1) * 32, n0 = (wid & 1) * 64;
    const u32 a_base  = (u32)__cvta_generic_to_shared(Ash);
    const u32 al_base = (u32)__cvta_generic_to_shared(Alos);
    const u32 w_base  = (u32)__cvta_generic_to_shared(Wsh);
    const u32 wl_base = (u32)__cvta_generic_to_shared(Wlos);
    const int a_i = lane & 7, a_sel = lane >> 3;
    const int a_row = ((a_sel & 1) ? 8 : 0) + a_i;
    const int a_kof = (a_sel & 2) ? 8 : 0;
    const int b_row = lane & 15;

    float acc[2][8][4];
#pragma unroll
    for (int mt = 0; mt < 2; mt++)
#pragma unroll
        for (int nt = 0; nt < 8; nt++)
#pragma unroll
            for (int q = 0; q < 4; q++) acc[mt][nt][q] = 0.f;

#pragma unroll
    for (int k0 = 0; k0 < DD; k0 += 16) {
        u32 ah[2][4], al[2][4], bh[8][2], bl[8][2];
#pragma unroll
        for (int mt = 0; mt < 2; mt++) {
            const u32 off = (u32)((m0 + mt * 16 + a_row) * (LDAB * 2) + (k0 + a_kof) * 2);
            ldsm4(ah[mt], a_base + off);
            ldsm4(al[mt], al_base + off);
        }
#pragma unroll
        for (int nt = 0; nt < 8; nt++) {
            const u32 off = (u32)((k0 + b_row) * (LDAB * 2) + (n0 + nt * 8) * 2);
            ldsm2t(bh[nt], w_base + off);
            ldsm2t(bl[nt], wl_base + off);
        }
#pragma unroll
        for (int mt = 0; mt < 2; mt++)
#pragma unroll
            for (int nt = 0; nt < 8; nt++) {
                mma16816(acc[mt][nt], ah[mt], bh[nt]);
                mma16816(acc[mt][nt], ah[mt], bl[nt]);
                mma16816(acc[mt][nt], al[mt], bh[nt]);
            }
    }

    __syncthreads();
    {
        const int g = lane >> 2, t = lane & 3;
#pragma unroll
        for (int mt = 0; mt < 2; mt++)
#pragma unroll
            for (int nt = 0; nt < 8; nt++) {
                const int row = m0 + mt * 16 + g;
                const int col = n0 + nt * 8 + 2 * t;
                *(float2*)(Csh + row * LDC + col)       = make_float2(acc[mt][nt][0], acc[mt][nt][1]);
                *(float2*)(Csh + (row + 8) * LDC + col) = make_float2(acc[mt][nt][2], acc[mt][nt][3]);
            }
    }
    __syncthreads();

    const float4 bias4 = *(const float4*)(bias + lane * 4);
#pragma unroll
    for (int i = 0; i < 16; i++) {
        const int lr = wid * 16 + i;
        const int r = row0 + lr;
        if (r >= NN) continue;
        float4 o = *(const float4*)(Csh + lr * LDC + lane * 4);
        o.x = siluf(o.x + bias4.x);
        o.y = siluf(o.y + bias4.y);
        o.z = siluf(o.z + bias4.z);
        o.w = siluf(o.w + bias4.w);
        *(float4*)(outf + (size_t)r * DD + lane * 4) = o;
    }
}

// ---------------- gather v4: row sum -> h1 (fp32) ----------------
// agg = dn*(c2b[n] + sum c2b[r]);  h1[n] = h[n] + ag*silu(agg + convB)
__global__ void __launch_bounds__(256) gather_kernel(
    const int* __restrict__ off, const int* __restrict__ eidx,
    const float* __restrict__ dinv, const __nv_bfloat16* __restrict__ c2b,
    const float* __restrict__ hbuf, const float* __restrict__ convB,
    const float* __restrict__ alpha_g,
    float* __restrict__ h1buf)
{
    const int n = blockIdx.x * 8 + (threadIdx.x >> 5);
    if (n >= NN) return;
    const int lane = threadIdx.x & 31;
    const int half = lane >> 4;
    const int hl   = lane & 15;
    const int s = __ldg(off + n), e = __ldg(off + n + 1);
    const float dn = __ldg(dinv + n);

    float acc[8];
    {
        uint4 u = *(const uint4*)(c2b + (size_t)n * DD + hl * 8);
        float f[8]; unp8(u, f);
        const float w0 = (half == 0) ? 1.f : 0.f;
#pragma unroll
        for (int i = 0; i < 8; i++) acc[i] = w0 * f[i];
    }

    for (int j0 = s; j0 < e; j0 += 32) {
        const int jn = min(32, e - j0);
        int eid = 0;
        if (lane < jn) eid = __ldg(eidx + j0 + lane);
        for (int t = 0; t < jn; t += 8) {
            int rr[4]; float ww[4]; uint4 vv[4];
#pragma unroll
            for (int q = 0; q < 4; q++) {
                const int idx = t + 2 * q + half;
                const int src = idx & 31;
                int r = __shfl_sync(0xffffffffu, eid, src);
                const bool act = idx < jn;
                rr[q] = act ? r : 0;
                ww[q] = act ? 1.f : 0.f;
            }
#pragma unroll
            for (int q = 0; q < 4; q++)
                vv[q] = __ldg((const uint4*)(c2b + (size_t)rr[q] * DD + hl * 8));
#pragma unroll
            for (int q = 0; q < 4; q++) {
                float f[8]; unp8(vv[q], f);
#pragma unroll
                for (int i = 0; i < 8; i++) acc[i] = fmaf(ww[q], f[i], acc[i]);
            }
        }
    }

    const float ag = __ldg(alpha_g);
#pragma unroll
    for (int i = 0; i < 8; i++) {
        acc[i] += __shfl_xor_sync(0xffffffffu, acc[i], 16);
        acc[i] *= dn;
    }
    if (half == 0) {
        float4 hA = *(const float4*)(hbuf + (size_t)n * DD + hl * 8);
        float4 hB = *(const float4*)(hbuf + (size_t)n * DD + hl * 8 + 4);
        const float4 cA = *(const float4*)(convB + hl * 8);
        const float4 cB = *(const float4*)(convB + hl * 8 + 4);
        float4 oA, oB;
        oA.x = fmaf(ag, siluf(acc[0] + cA.x), hA.x);
        oA.y = fmaf(ag, siluf(acc[1] + cA.y), hA.y);
        oA.z = fmaf(ag, siluf(acc[2] + cA.z), hA.z);
        oA.w = fmaf(ag, siluf(acc[3] + cA.w), hA.w);
        oB.x = fmaf(ag, siluf(acc[4] + cB.x), hB.x);
        oB.y = fmaf(ag, siluf(acc[5] + cB.y), hB.y);
        oB.z = fmaf(ag, siluf(acc[6] + cB.z), hB.z);
        oB.w = fmaf(ag, siluf(acc[7] + cB.w), hB.w);
        *(float4*)(h1buf + (size_t)n * DD + hl * 8)     = oA;
        *(float4*)(h1buf + (size_t)n * DD + hl * 8 + 4) = oB;
    }
}

// ---------------- final: logits + log_softmax ----------------
__global__ void __launch_bounds__(128) final_kernel(
    const float* __restrict__ h, const float* __restrict__ Wf,
    const float* __restrict__ fb, float* __restrict__ out)
{
    __shared__ float Wsh[DD * CC];
    __shared__ float bsh[CC];
    __shared__ float rowbuf[4][DD];
    const int tid = threadIdx.x;
    for (int i = tid; i < DD * CC; i += 128) Wsh[i] = Wf[i];
    if (tid < CC) bsh[tid] = fb[tid];
    __syncthreads();

    const int wid = tid >> 5, lane = tid & 31;
    const int rbase = blockIdx.x * 32 + wid * 8;
    const bool has1 = (lane < CC - 32);

    for (int ri = 0; ri < 8; ri++) {
        const int r = rbase + ri;
        if (r >= NN) return;
        float4 v = *(const float4*)(h + (size_t)r * DD + lane * 4);
        *(float4*)(&rowbuf[wid][lane * 4]) = v;
        __syncwarp();
        float acc0 = bsh[lane];
        float acc1 = has1 ? bsh[32 + lane] : 0.f;
#pragma unroll 4
        for (int k = 0; k < DD; k++) {
            float hv = rowbuf[wid][k];
            acc0 = fmaf(hv, Wsh[k * CC + lane], acc0);
            if (has1) acc1 = fmaf(hv, Wsh[k * CC + 32 + lane], acc1);
        }
        float m = has1 ? fmaxf(acc0, acc1) : acc0;
#pragma unroll
        for (int o = 16; o > 0; o >>= 1) m = fmaxf(m, __shfl_xor_sync(0xffffffffu, m, o));
        float s = expf(acc0 - m) + (has1 ? expf(acc1 - m) : 0.f);
#pragma unroll
        for (int o = 16; o > 0; o >>= 1) s += __shfl_xor_sync(0xffffffffu, s, o);
        const float ls = logf(s);
        out[(size_t)r * CC + lane] = acc0 - m - ls;
        if (has1) out[(size_t)r * CC + 32 + lane] = acc1 - m - ls;
        __syncwarp();
    }
}

// ---------------- launch ----------------
extern "C" void kernel_launch(void* const* d_in, const int* in_sizes, int n_in,
                              void* d_out, int out_size)
{
    const float* x       = (const float*)d_in[0];
    const int*   ei      = (const int*)  d_in[1];
    const float* start_W = (const float*)d_in[2];
    const float* start_b = (const float*)d_in[3];
    const float* ln1_g   = (const float*)d_in[4];
    const float* ln1_b   = (const float*)d_in[5];
    const float* convW   = (const float*)d_in[6];
    const float* convB   = (const float*)d_in[7];
    const float* alpha_g = (const float*)d_in[8];
    const float* ln2_g   = (const float*)d_in[9];
    const float* ln2_b   = (const float*)d_in[10];
    const float* ffwW    = (const float*)d_in[11];
    const float* ffwB    = (const float*)d_in[12];
    const float* alpha_f = (const float*)d_in[13];
    const float* final_W = (const float*)d_in[14];
    const float* final_b = (const float*)d_in[15];
    float* out = (float*)d_out;

    float *h, *h1, *dinv;
    __nv_bfloat16 *c2b, *wb, *w0hi, *w0lo;
    int *counts, *off, *cur, *eidx, *part;
    cudaGetSymbolAddress((void**)&h, g_h);
    cudaGetSymbolAddress((void**)&h1, g_h1);
    cudaGetSymbolAddress((void**)&c2b, g_c2b);
    cudaGetSymbolAddress((void**)&wb, g_wb);
    cudaGetSymbolAddress((void**)&w0hi, g_w0hi);
    cudaGetSymbolAddress((void**)&w0lo, g_w0lo);
    cudaGetSymbolAddress((void**)&dinv, g_dinv);
    cudaGetSymbolAddress((void**)&counts, g_counts);
    cudaGetSymbolAddress((void**)&off, g_off);
    cudaGetSymbolAddress((void**)&cur, g_cur);
    cudaGetSymbolAddress((void**)&eidx, g_eidx);
    cudaGetSymbolAddress((void**)&part, g_part);

    const int* rowi = ei;
    const int* coli = ei + NE;

    cudaFuncSetAttribute(gemm0_kernel, cudaFuncAttributeMaxDynamicSharedMemorySize, SM_M0);
    cudaFuncSetAttribute(gemm1_kernel, cudaFuncAttributeMaxDynamicSharedMemorySize, SM_G1);
    cudaFuncSetAttribute(gemm2_kernel, cudaFuncAttributeMaxDynamicSharedMemorySize, SM_G2);

    const int G1 = (NN + 127) / 128;
    const int NW = DD * DD + 2 * NL * DD * DD;

    // capture slot #4 = count (control: 14.5us)
    convert_w_kernel<<<(NW + 255) / 256, 256>>>(start_W, convW, ffwW, w0hi, w0lo, wb);   // 1
    gemm0_kernel<<<G1, 256, SM_M0>>>(x, w0hi, w0lo, start_b, h);                          // 2
    zero_counts_kernel<<<(NN + 255) / 256, 256>>>(counts);                                // 3
    count_kernel<<<(NE + 255) / 256, 256>>>(coli, counts);                                // 4 (capture)
    dinv_kernel<<<(NN + 255) / 256, 256>>>(counts, dinv);                                 // 5
    gemm1_kernel<<<G1, 256, SM_G1>>>(h, wb, ln1_g, ln1_b, dinv, c2b);                     // 6
    scan_block_kernel<<<NB_SCAN, 1024>>>(counts, off, part);                              // 7
    scan_part_kernel<<<1, 32>>>(part, off);                                               // 8
    add_carry_kernel<<<(NN + 255) / 256, 256>>>(counts, off, part, cur);                  // 9
    fill_kernel<<<(NE + 255) / 256, 256>>>(rowi, coli, cur, eidx);                        // 10

    for (int i = 0; i < NL; i++) {
        if (i > 0)
            gemm1_kernel<<<G1, 256, SM_G1>>>(h, wb + (size_t)i * DD * DD,
                                             ln1_g + i * DD, ln1_b + i * DD, dinv, c2b);
        gather_kernel<<<(NN + 7) / 8, 256>>>(off, eidx, dinv, c2b, h, convB + i * DD,
                                             alpha_g + i, h1);
        gemm2_kernel<<<G1, 256, SM_G2>>>(h1, wb + (size_t)(NL + i) * DD * DD,
                                         ffwB + i * DD,
                                         ln2_g + i * DD, ln2_b + i * DD,
                                         alpha_f + i, h);
    }

    final_kernel<<<(NN + 31) / 32, 128>>>(h, final_W, final_b, out);
}